// round 15
// baseline (speedup 1.0000x reference)
#include <cuda_runtime.h>
#include <cuda_fp16.h>
#include <math.h>
#include <stdint.h>

#define BB 2
#define TT 2048
#define CC 1024
#define HH 16
#define DH 64
#define NROWS (BB*TT)          // 4096

// ================= static scratch =================
__device__ __half g_y [NROWS*CC];       // attention output, fp16
__device__ float g_x1 [NROWS*CC];
__device__ float g_mu [NROWS];
__device__ float g_inv[NROWS];

__device__ __half g_xt_h[NROWS*CC], g_xt_l[NROWS*CC];
__device__ __half g_yh [NROWS*CC];
__device__ __half g_hh [NROWS*CC];
__device__ __half g_fch[NROWS*4*CC];

__device__ __half g_qh[NROWS*CC], g_ql[NROWS*CC];
__device__ __half g_kh[NROWS*CC], g_kl[NROWS*CC];
__device__ __half g_v [NROWS*CC];

__device__ __half g_wattn_h[3*CC*CC], g_wattn_l[3*CC*CC];
__device__ __half g_waproj[CC*CC];
__device__ __half g_wfc   [4*CC*CC];
__device__ __half g_wmproj[CC*4*CC];

#define QSCALE 0.18033688011112042f   // 0.125 * log2(e)

// ================= helpers =================
__device__ __forceinline__ uint32_t smem_u32(const void* p) {
    uint32_t a;
    asm("{ .reg .u64 t; cvta.to.shared.u64 t, %1; cvt.u32.u64 %0, t; }" : "=r"(a) : "l"(p));
    return a;
}
#define SWZ(x) ((x) ^ (((x) >> 3) & 0x70))

__device__ __forceinline__ void cp16(uint32_t sa, const void* g) {
    asm volatile("cp.async.cg.shared.global [%0], [%1], 16;" :: "r"(sa), "l"(g));
}
#define CP_COMMIT() asm volatile("cp.async.commit_group;" ::: "memory")
template <int N> __device__ __forceinline__ void cpwait() {
    asm volatile("cp.async.wait_group %0;" :: "n"(N) : "memory");
}

__device__ __forceinline__ void ldsm4(uint32_t& r0, uint32_t& r1, uint32_t& r2, uint32_t& r3, uint32_t a) {
    asm volatile("ldmatrix.sync.aligned.m8n8.x4.shared.b16 {%0,%1,%2,%3}, [%4];"
        : "=r"(r0), "=r"(r1), "=r"(r2), "=r"(r3) : "r"(a));
}
__device__ __forceinline__ void ldsm4t(uint32_t& r0, uint32_t& r1, uint32_t& r2, uint32_t& r3, uint32_t a) {
    asm volatile("ldmatrix.sync.aligned.m8n8.x4.trans.shared.b16 {%0,%1,%2,%3}, [%4];"
        : "=r"(r0), "=r"(r1), "=r"(r2), "=r"(r3) : "r"(a));
}
__device__ __forceinline__ void mma_fp(float* c, const uint32_t* a, const uint32_t* b) {
    asm volatile("mma.sync.aligned.m16n8k16.row.col.f32.f16.f16.f32 "
        "{%0,%1,%2,%3}, {%4,%5,%6,%7}, {%8,%9}, {%0,%1,%2,%3};"
        : "+f"(c[0]), "+f"(c[1]), "+f"(c[2]), "+f"(c[3])
        : "r"(a[0]), "r"(a[1]), "r"(a[2]), "r"(a[3]), "r"(b[0]), "r"(b[1]));
}
__device__ __forceinline__ float ex2f(float x) {
    float r; asm("ex2.approx.f32 %0, %1;" : "=f"(r) : "f"(x)); return r;
}
__device__ __forceinline__ void split2h(float v, __half& h, __half& l) {
    h = __float2half(v);
    l = __float2half(v - __half2float(h));
}
__device__ __forceinline__ uint32_t pack2h(__half a, __half b) {
    __half2 t(a, b); return *reinterpret_cast<uint32_t*>(&t);
}

// ================= block reduce (256 thr, up to 5 scalars) =================
__device__ __forceinline__ void block_reduce(float* vals, int n, float* scr) {
    int tid = threadIdx.x, lane = tid & 31, wid = tid >> 5;
    for (int k = 0; k < n; k++) {
        float v = vals[k];
        #pragma unroll
        for (int o = 16; o; o >>= 1) v += __shfl_xor_sync(0xffffffffu, v, o);
        if (lane == 0) scr[k*8 + wid] = v;
    }
    __syncthreads();
    if (tid == 0) {
        for (int k = 0; k < n; k++) {
            float s = 0.f;
            #pragma unroll
            for (int w = 0; w < 8; w++) s += scr[k*8 + w];
            scr[40 + k] = s;
        }
    }
    __syncthreads();
    for (int k = 0; k < n; k++) vals[k] = scr[40 + k];
    __syncthreads();
}

// ================= LayerNorm (fp16 out, row cached in smem) =================
__global__ void ln_half_kernel(const float* __restrict__ x, const float* __restrict__ w,
                               const float* __restrict__ b, __half* __restrict__ o) {
    __shared__ float scr[48];
    __shared__ float xr_s[CC];
    int row = blockIdx.x;
    const float* xr = x + (size_t)row * CC;
    int tid = threadIdx.x;
    float v2[2] = {0.f, 0.f};
    for (int i = tid; i < CC; i += 256) {
        float v = xr[i]; xr_s[i] = v;
        v2[0] += v; v2[1] += v*v;
    }
    block_reduce(v2, 2, scr);
    float mean = v2[0] * (1.0f/CC);
    float var  = v2[1] * (1.0f/CC) - mean*mean;
    float inv  = rsqrtf(var + 1e-5f);
    size_t base = (size_t)row * CC;
    for (int i = tid; i < CC; i += 256)
        o[base + i] = __float2half((xr_s[i] - mean) * inv * w[i] + b[i]);
}

// ================= fused LN1 + logmap -> fp16 pair; exports ref-row LN stats =================
__global__ void logmap_fused(const float* __restrict__ x,
                             const float* __restrict__ w, const float* __restrict__ b,
                             __half* __restrict__ oh, __half* __restrict__ ol,
                             float* __restrict__ mu_out, float* __restrict__ inv_out) {
    __shared__ float scr[48];
    __shared__ float un[CC], an[CC];
    int row = blockIdx.x;
    int t = row & (TT - 1);
    const float* xu = x + (size_t)row * CC;
    const float* xa = (t == 0) ? nullptr : xu - CC;
    int tid = threadIdx.x;

    float v4[4] = {0.f, 0.f, 0.f, 0.f};
    for (int i = tid; i < CC; i += 256) {
        float vu = xu[i]; un[i] = vu; v4[0] += vu; v4[1] += vu*vu;
        float va = xa ? xa[i] : 0.f;  an[i] = va;
        v4[2] += va; v4[3] += va*va;
    }
    block_reduce(v4, 4, scr);
    float mu_u = v4[0] * (1.0f/CC);
    float inv_u = rsqrtf(v4[1] * (1.0f/CC) - mu_u*mu_u + 1e-5f);
    float mu_a = v4[2] * (1.0f/CC);
    float inv_a = rsqrtf(fmaxf(v4[3] * (1.0f/CC) - mu_a*mu_a, 0.f) + 1e-5f);
    if (tid == 0) { mu_out[row] = mu_a; inv_out[row] = inv_a; }

    float v3[3] = {0.f, 0.f, 0.f};
    for (int i = tid; i < CC; i += 256) {
        float ui = (un[i] - mu_u) * inv_u * w[i] + b[i];
        float ai = xa ? ((an[i] - mu_a) * inv_a * w[i] + b[i]) : 0.f;
        un[i] = ui; an[i] = ai;
        v3[0] += ai*ai; v3[1] += ui*ui; v3[2] += ai*ui;
    }
    block_reduce(v3, 3, scr);
    float an2 = v3[0], un2 = v3[1], ipau = v3[2];

    float coefX = 1.f - 2.f*ipau + un2;
    float coefU = 1.f - an2;
    float rden  = 1.f / (1.f - 2.f*ipau + an2*un2);

    float mn2v[1] = {0.f};
    for (int i = tid; i < CC; i += 256) {
        float mi = (coefU * un[i] - coefX * an[i]) * rden;
        an[i] = mi;
        mn2v[0] += mi*mi;
    }
    block_reduce(mn2v, 1, scr);
    float mn = sqrtf(mn2v[0]);
    float cf = 1.f + an2;
    float arg = fminf(sqrtf(mn), 0.999f);
    float scale = cf * atanhf(arg) / mn;
    size_t base = (size_t)row * CC;
    for (int i = tid; i < CC; i += 256) {
        __half h, l; split2h(scale * an[i], h, l);
        oh[base + i] = h; ol[base + i] = l;
    }
}

// ================= fused LN1(row-1) + expmap (stats forwarded, y fp16) =================
__global__ void expmap_fused(const float* __restrict__ x,
                             const float* __restrict__ w, const float* __restrict__ b,
                             const __half* __restrict__ y, __half* __restrict__ o,
                             const float* __restrict__ mu_in, const float* __restrict__ inv_in) {
    __shared__ float scr[48];
    __shared__ float rf[CC], vv[CC];
    int row = blockIdx.x;
    int t = row & (TT - 1);
    const float* xa = (t == 0) ? nullptr : x + (size_t)(row - 1) * CC;
    const __half* v = y + (size_t)row * CC;
    int tid = threadIdx.x;

    float mu_a = mu_in[row], inv_a = inv_in[row];

    float v3[3] = {0.f, 0.f, 0.f};
    for (int i = tid; i < CC; i += 256) {
        float xi = xa ? ((xa[i] - mu_a) * inv_a * w[i] + b[i]) : 0.f;
        rf[i] = xi;
        float vi = __half2float(v[i]);
        vv[i] = vi;
        v3[0] += xi*xi; v3[1] += vi*vi; v3[2] += xi*vi;
    }
    block_reduce(v3, 3, scr);
    float refn2 = v3[0], vn2 = v3[1], xv = v3[2];

    float lam = 2.f / (1.f + refn2);
    float vn  = sqrtf(vn2);
    float th  = tanhf(sqrtf(lam * vn2 * 0.5f));
    float ss  = th / vn;
    float secn2 = th * th;
    float ipxs  = ss * xv;
    float coefX = 1.f + 2.f*ipxs + secn2;
    float coefY = (1.f - refn2) * ss;
    float rden  = 1.f / (1.f + 2.f*ipxs + refn2*secn2);
    size_t base = (size_t)row * CC;
    for (int i = tid; i < CC; i += 256)
        o[base + i] = __float2half((coefX * rf[i] + coefY * vv[i]) * rden);
}

// ================= weight transpose kernels =================
__global__ void wsplit_h_kernel(const float* __restrict__ W,
                                __half* __restrict__ Wh, __half* __restrict__ Wl,
                                int K, int N) {
    __shared__ float t[32][33];
    int n0 = blockIdx.x * 32, k0 = blockIdx.y * 32;
    int tx = threadIdx.x, ty = threadIdx.y;
    #pragma unroll
    for (int j = 0; j < 32; j += 8)
        t[ty + j][tx] = W[(size_t)(k0 + ty + j) * N + n0 + tx];
    __syncthreads();
    bool needs_lo = (n0 < 2*CC);
    #pragma unroll
    for (int j = 0; j < 32; j += 8) {
        float v = t[tx][ty + j];
        __half h, l; split2h(v, h, l);
        size_t o = (size_t)(n0 + ty + j) * K + k0 + tx;
        Wh[o] = h;
        if (needs_lo) Wl[o] = l;
    }
}

__global__ void wtrans_h_kernel(const float* __restrict__ W, __half* __restrict__ Wt,
                                int K, int N) {
    __shared__ float t[32][33];
    int n0 = blockIdx.x * 32, k0 = blockIdx.y * 32;
    int tx = threadIdx.x, ty = threadIdx.y;
    #pragma unroll
    for (int j = 0; j < 32; j += 8)
        t[ty + j][tx] = W[(size_t)(k0 + ty + j) * N + n0 + tx];
    __syncthreads();
    #pragma unroll
    for (int j = 0; j < 32; j += 8)
        Wt[(size_t)(n0 + ty + j) * K + k0 + tx] = __float2half(t[tx][ty + j]);
}

// ================= shared tile loader (256 threads) =================
#define TILEB 16384
__device__ __forceinline__ void load_tile(uint32_t sdst, const void* gv,
                                          int row0, int Kd, int k0, int tid) {
    const __half* base = (const __half*)gv + (size_t)row0 * Kd + k0;
    #pragma unroll
    for (int i = 0; i < 4; i++) {
        int idx = tid * 4 + i;
        int r = idx >> 3, gc = idx & 7;
        uint32_t so = sdst + SWZ((uint32_t)(r * 128 + gc * 16));
        cp16(so, base + (size_t)r * Kd + gc * 8);
    }
}

// ================= QKV GEMM: 256 thr, 8 warps (2x4), warptile 64x32, 3-stage =================
#define QSTAGEB (4*TILEB)
#define QGSMEM (3*QSTAGEB)

__global__ void __launch_bounds__(256, 1) gemm_qkv(
    const __half* __restrict__ Ah, const __half* __restrict__ Al,
    const __half* __restrict__ Bh, const __half* __restrict__ Bl,
    const float* __restrict__ bias,
    __half* __restrict__ Cqh, __half* __restrict__ Cql,
    __half* __restrict__ Ckh, __half* __restrict__ Ckl,
    __half* __restrict__ Cv)
{
    const int Kd = CC;
    extern __shared__ __align__(1024) char smem[];
    uint32_t sb = smem_u32(smem);
    int tid = threadIdx.x, wid = tid >> 5, lane = tid & 31;
    int wm = wid >> 2, wn = wid & 3;
    int bm = blockIdx.y * 128, bn = blockIdx.x * 128;
    const bool full = (bn < 2*CC);

    float acc[4][4][4];
    #pragma unroll
    for (int mt = 0; mt < 4; mt++)
        #pragma unroll
        for (int nt = 0; nt < 4; nt++)
            #pragma unroll
            for (int r = 0; r < 4; r++) acc[mt][nt][r] = 0.f;

    const int nch = Kd >> 6;

    #pragma unroll
    for (int s = 0; s < 3; s++) {
        uint32_t st = sb + s * QSTAGEB;
        int k0 = s * 64;
        load_tile(st,           Ah, bm, Kd, k0, tid);
        load_tile(st + 2*TILEB, Bh, bn, Kd, k0, tid);
        if (full) {
            load_tile(st +   TILEB, Al, bm, Kd, k0, tid);
            load_tile(st + 3*TILEB, Bl, bn, Kd, k0, tid);
        }
        CP_COMMIT();
    }

    int grp = lane >> 3, rw = lane & 7;
    int a_row = (grp & 1) * 8 + rw;
    int a_kb  = (grp >> 1) * 16;
    int b_row = (grp >> 1) * 8 + rw;
    int b_kb  = (grp & 1) * 16;

    for (int c = 0; c < nch; c++) {
        int rem = nch - 1 - c;
        if (rem >= 2) cpwait<2>(); else if (rem == 1) cpwait<1>(); else cpwait<0>();
        __syncthreads();
        uint32_t st = sb + (c % 3) * QSTAGEB;
        uint32_t Ahs = st, Als = st + TILEB, Bhs = st + 2*TILEB, Bls = st + 3*TILEB;

        #pragma unroll
        for (int kk = 0; kk < 4; kk++) {
            uint32_t ah[4][4], al[4][4], bh[4][2], bl[4][2];
            #pragma unroll
            for (int mt = 0; mt < 4; mt++) {
                uint32_t off = SWZ((uint32_t)((wm*64 + mt*16 + a_row) * 128 + kk*32 + a_kb));
                ldsm4(ah[mt][0], ah[mt][1], ah[mt][2], ah[mt][3], Ahs + off);
                if (full) ldsm4(al[mt][0], al[mt][1], al[mt][2], al[mt][3], Als + off);
            }
            #pragma unroll
            for (int p = 0; p < 2; p++) {
                uint32_t off = SWZ((uint32_t)((wn*32 + p*16 + b_row) * 128 + kk*32 + b_kb));
                ldsm4(bh[2*p][0], bh[2*p][1], bh[2*p+1][0], bh[2*p+1][1], Bhs + off);
                if (full) ldsm4(bl[2*p][0], bl[2*p][1], bl[2*p+1][0], bl[2*p+1][1], Bls + off);
            }
            #pragma unroll
            for (int mt = 0; mt < 4; mt++)
                #pragma unroll
                for (int nt = 0; nt < 4; nt++) {
                    mma_fp(acc[mt][nt], ah[mt], bh[nt]);
                    if (full) {
                        mma_fp(acc[mt][nt], ah[mt], bl[nt]);
                        mma_fp(acc[mt][nt], al[mt], bh[nt]);
                    }
                }
        }
        __syncthreads();
        int cn = c + 3;
        if (cn < nch) {
            uint32_t sd = sb + (cn % 3) * QSTAGEB;
            int k0 = cn * 64;
            load_tile(sd,           Ah, bm, Kd, k0, tid);
            load_tile(sd + 2*TILEB, Bh, bn, Kd, k0, tid);
            if (full) {
                load_tile(sd +   TILEB, Al, bm, Kd, k0, tid);
                load_tile(sd + 3*TILEB, Bl, bn, Kd, k0, tid);
            }
            CP_COMMIT();
        }
    }

    int r0 = lane >> 2, c0 = (lane & 3) * 2;
    #pragma unroll
    for (int mt = 0; mt < 4; mt++) {
        #pragma unroll
        for (int nt = 0; nt < 4; nt++) {
            int col = bn + wn*32 + nt*8 + c0;
            float b0 = bias[col], b1 = bias[col + 1];
            int part = col >> 10;
            int head = (col >> 6) & 15;
            int d    = col & 63;
            #pragma unroll
            for (int half = 0; half < 2; half++) {
                int row = bm + wm*64 + mt*16 + r0 + half*8;
                float v0 = acc[mt][nt][half*2]     + b0;
                float v1 = acc[mt][nt][half*2 + 1] + b1;
                size_t off = ((((size_t)(row >> 11)) * 16 + head) * TT + (row & 2047)) * 64 + d;
                if (part == 2) {
                    *reinterpret_cast<__half2*>(Cv + off) =
                        __half2(__float2half(v0), __float2half(v1));
                } else {
                    if (part == 0) { v0 *= QSCALE; v1 *= QSCALE; }
                    __half h0, l0, h1, l1;
                    split2h(v0, h0, l0); split2h(v1, h1, l1);
                    __half* Dh = (part == 0) ? Cqh : Ckh;
                    __half* Dl = (part == 0) ? Cql : Ckl;
                    *reinterpret_cast<__half2*>(Dh + off) = __half2(h0, h1);
                    *reinterpret_cast<__half2*>(Dl + off) = __half2(l0, l1);
                }
            }
        }
    }
}

// ================= fp16 x1 GEMM: 256 thr, 8 warps (2x4), 2-stage =================
#define F1STAGE (2*TILEB)
#define F1SMEM (2*F1STAGE)

template<int EPI>
__global__ void __launch_bounds__(256, 2) gemm_fp16(
    const __half* __restrict__ A, const __half* __restrict__ B,
    const float* __restrict__ bias, const float* __restrict__ res,
    float* __restrict__ Cf, __half* __restrict__ Co,
    int Nd, int Kd)
{
    extern __shared__ __align__(1024) char smem[];
    uint32_t sb = smem_u32(smem);
    int tid = threadIdx.x, wid = tid >> 5, lane = tid & 31;
    int wm = wid >> 2, wn = wid & 3;
    int bm = blockIdx.y * 128, bn = blockIdx.x * 128;

    float acc[4][4][4];
    #pragma unroll
    for (int mt = 0; mt < 4; mt++)
        #pragma unroll
        for (int nt = 0; nt < 4; nt++)
            #pragma unroll
            for (int r = 0; r < 4; r++) acc[mt][nt][r] = 0.f;

    int nch = Kd >> 6;

    #pragma unroll
    for (int s = 0; s < 2; s++) {
        uint32_t st = sb + s * F1STAGE;
        int k0 = s * 64;
        load_tile(st,         A, bm, Kd, k0, tid);
        load_tile(st + TILEB, B, bn, Kd, k0, tid);
        CP_COMMIT();
    }

    int grp = lane >> 3, rw = lane & 7;
    int a_row = (grp & 1) * 8 + rw;
    int a_kb  = (grp >> 1) * 16;
    int b_row = (grp >> 1) * 8 + rw;
    int b_kb  = (grp & 1) * 16;

    for (int c = 0; c < nch; c++) {
        if (c + 1 < nch) cpwait<1>(); else cpwait<0>();
        __syncthreads();
        uint32_t st = sb + (c & 1) * F1STAGE;
        uint32_t As = st, Bs = st + TILEB;

        #pragma unroll
        for (int kk = 0; kk < 4; kk++) {
            uint32_t af[4][4], bf[4][2];
            #pragma unroll
            for (int mt = 0; mt < 4; mt++) {
                uint32_t off = SWZ((uint32_t)((wm*64 + mt*16 + a_row) * 128 + kk*32 + a_kb));
                ldsm4(af[mt][0], af[mt][1], af[mt][2], af[mt][3], As + off);
            }
            #pragma unroll
            for (int p = 0; p < 2; p++) {
                uint32_t off = SWZ((uint32_t)((wn*32 + p*16 + b_row) * 128 + kk*32 + b_kb));
                ldsm4(bf[2*p][0], bf[2*p][1], bf[2*p+1][0], bf[2*p+1][1], Bs + off);
            }
            #pragma unroll
            for (int mt = 0; mt < 4; mt++)
                #pragma unroll
                for (int nt = 0; nt < 4; nt++)
                    mma_fp(acc[mt][nt], af[mt], bf[nt]);
        }
        __syncthreads();
        int cn = c + 2;
        if (cn < nch) {
            int k0 = cn * 64;
            load_tile(st,         A, bm, Kd, k0, tid);
            load_tile(st + TILEB, B, bn, Kd, k0, tid);
            CP_COMMIT();
        }
    }

    int r0 = lane >> 2, c0 = (lane & 3) * 2;
    #pragma unroll
    for (int mt = 0; mt < 4; mt++) {
        #pragma unroll
        for (int nt = 0; nt < 4; nt++) {
            int col = bn + wn*32 + nt*8 + c0;
            float b0 = bias[col], b1 = bias[col + 1];
            #pragma unroll
            for (int half = 0; half < 2; half++) {
                int row = bm + wm*64 + mt*16 + r0 + half*8;
                float v0 = acc[mt][nt][half*2]     + b0;
                float v1 = acc[mt][nt][half*2 + 1] + b1;
                size_t off = (size_t)row * Nd + col;
                if (EPI == 2) {
                    v0 = v0 * normcdff(v0);
                    v1 = v1 * normcdff(v1);
                    *reinterpret_cast<__half2*>(Co + off) =
                        __half2(__float2half(v0), __float2half(v1));
                } else {
                    v0 += res[off]; v1 += res[off + 1];
                    *reinterpret_cast<float2*>(Cf + off) = make_float2(v0, v1);
                }
            }
        }
    }
}

// ================= flash attention: QK fp16x3, PV fp16x1, fp16 out, 3-stage KV =================
#define ATSTG 24576
#define AT_SMEM (32768 + 3*ATSTG)   // 106496

__device__ __forceinline__ void load_kv(uint32_t st,
        const __half* khp, const __half* klp,
        const __half* vp, int kt, int tid) {
    int k0 = kt * 64;
    #pragma unroll
    for (int i = 0; i < 2; i++) {
        int idx = tid * 2 + i;
        int r = idx >> 3, gc = idx & 7;
        uint32_t off = SWZ((uint32_t)(r * 128 + gc * 16));
        size_t g = (size_t)(k0 + r) * 64 + gc * 8;
        cp16(st + off,         khp + g);
        cp16(st + 8192 + off,  klp + g);
        cp16(st + 16384 + off, vp + g);
    }
}

__global__ void __launch_bounds__(256, 1) attn_hmma(
    const __half* __restrict__ Qh, const __half* __restrict__ Ql,
    const __half* __restrict__ Kh, const __half* __restrict__ Kl,
    const __half* __restrict__ V,
    __half* __restrict__ y)
{
    extern __shared__ __align__(1024) char smem[];
    uint32_t sb = smem_u32(smem);
    int tid = threadIdx.x, wid = tid >> 5, lane = tid & 31;
    int bhx = blockIdx.y, b = bhx >> 4, h = bhx & 15;
    int qblk = gridDim.x - 1 - blockIdx.x;
    int q0 = qblk * 128;
    size_t hb = (size_t)bhx * TT * DH;
    const __half *qhp = Qh + hb, *qlp = Ql + hb;
    const __half *khp = Kh + hb, *klp = Kl + hb;
    const __half *vp = V + hb;

    uint32_t sQh = sb, sQl = sb + 16384;
    uint32_t kvb = sb + 32768;

    int ntiles = 2 * (qblk + 1);

    // prologue: group0 = Q + KV0; group1 = KV1; group2 = KV2 (empty groups legal)
    load_tile(sQh, qhp, q0, 64, 0, tid);
    load_tile(sQl, qlp, q0, 64, 0, tid);
    load_kv(kvb, khp, klp, vp, 0, tid);
    CP_COMMIT();
    if (ntiles > 1) load_kv(kvb + ATSTG, khp, klp, vp, 1, tid);
    CP_COMMIT();
    if (ntiles > 2) load_kv(kvb + 2*ATSTG, khp, klp, vp, 2, tid);
    CP_COMMIT();

    int grp = lane >> 3, rw = lane & 7;
    int a_row = (grp & 1) * 8 + rw, a_kb = (grp >> 1) * 16;
    int b_row = (grp >> 1) * 8 + rw, b_kb = (grp & 1) * 16;
    int v_row = (grp & 1) * 8 + rw,  v_db = (grp >> 1) * 16;

    // wait for group0 (Q + KV0); 2 groups may still be in flight
    cpwait<2>();
    __syncthreads();

    uint32_t qfh[4][4], qfl[4][4];
    #pragma unroll
    for (int kk = 0; kk < 4; kk++) {
        uint32_t off = SWZ((uint32_t)((wid*16 + a_row) * 128 + kk*32 + a_kb));
        ldsm4(qfh[kk][0], qfh[kk][1], qfh[kk][2], qfh[kk][3], sQh + off);
        ldsm4(qfl[kk][0], qfl[kk][1], qfl[kk][2], qfl[kk][3], sQl + off);
    }

    float o[8][4];
    #pragma unroll
    for (int nt = 0; nt < 8; nt++)
        #pragma unroll
        for (int r = 0; r < 4; r++) o[nt][r] = 0.f;
    float m0 = -1e30f, m1 = -1e30f, l0 = 0.f, l1 = 0.f;

    int qr0 = q0 + wid*16 + (lane >> 2);
    int kc0 = (lane & 3) * 2;

    for (int kt = 0; kt < ntiles; kt++) {
        if (kt > 0) {
            int rem = ntiles - 1 - kt;
            if (rem >= 2) cpwait<2>(); else if (rem == 1) cpwait<1>(); else cpwait<0>();
            __syncthreads();
        }
        uint32_t st = kvb + (kt % 3) * ATSTG;
        int k0 = kt * 64;
        if (k0 <= q0 + wid*16 + 15) {
            uint32_t sKh = st, sKl = st + 8192, sV = st + 16384;
            float s[8][4];
            #pragma unroll
            for (int nt = 0; nt < 8; nt++)
                #pragma unroll
                for (int r = 0; r < 4; r++) s[nt][r] = 0.f;

            #pragma unroll
            for (int kk = 0; kk < 4; kk++) {
                uint32_t bhf[8][2], blf[8][2];
                #pragma unroll
                for (int p = 0; p < 4; p++) {
                    uint32_t off = SWZ((uint32_t)((p*16 + b_row) * 128 + kk*32 + b_kb));
                    ldsm4(bhf[2*p][0], bhf[2*p][1], bhf[2*p+1][0], bhf[2*p+1][1], sKh + off);
                    ldsm4(blf[2*p][0], blf[2*p][1], blf[2*p+1][0], blf[2*p+1][1], sKl + off);
                }
                #pragma unroll
                for (int nt = 0; nt < 8; nt++) {
                    mma_fp(s[nt], qfh[kk], bhf[nt]);
                    mma_fp(s[nt], qfh[kk], blf[nt]);
                    mma_fp(s[nt], qfl[kk], bhf[nt]);
                }
            }

            if (k0 + 63 > qr0) {
                #pragma unroll
                for (int nt = 0; nt < 8; nt++) {
                    int kg = k0 + nt*8 + kc0;
                    if (kg     > qr0)     s[nt][0] = -1e30f;
                    if (kg + 1 > qr0)     s[nt][1] = -1e30f;
                    if (kg     > qr0 + 8) s[nt][2] = -1e30f;
                    if (kg + 1 > qr0 + 8) s[nt][3] = -1e30f;
                }
            }

            float t0 = -1e30f, t1 = -1e30f;
            #pragma unroll
            for (int nt = 0; nt < 8; nt++) {
                t0 = fmaxf(t0, fmaxf(s[nt][0], s[nt][1]));
                t1 = fmaxf(t1, fmaxf(s[nt][2], s[nt][3]));
            }
            t0 = fmaxf(t0, __shfl_xor_sync(0xffffffffu, t0, 1));
            t0 = fmaxf(t0, __shfl_xor_sync(0xffffffffu, t0, 2));
            t1 = fmaxf(t1, __shfl_xor_sync(0xffffffffu, t1, 1));
            t1 = fmaxf(t1, __shfl_xor_sync(0xffffffffu, t1, 2));
            float mn0 = fmaxf(m0, t0), mn1 = fmaxf(m1, t1);
            float al0 = ex2f(m0 - mn0), al1 = ex2f(m1 - mn1);
            m0 = mn0; m1 = mn1;

            float ps0 = 0.f, ps1 = 0.f;
            uint32_t pa[4][4];
            #pragma unroll
            for (int nt = 0; nt < 8; nt++) {
                float p0 = ex2f(s[nt][0] - m0), p1 = ex2f(s[nt][1] - m0);
                float p2 = ex2f(s[nt][2] - m1), p3 = ex2f(s[nt][3] - m1);
                ps0 += p0 + p1; ps1 += p2 + p3;
                int jj = nt >> 1, rb = (nt & 1) * 2;
                pa[jj][rb]   = pack2h(__float2half(p0), __float2half(p1));
                pa[jj][rb+1] = pack2h(__float2half(p2), __float2half(p3));
            }
            ps0 += __shfl_xor_sync(0xffffffffu, ps0, 1);
            ps0 += __shfl_xor_sync(0xffffffffu, ps0, 2);
            ps1 += __shfl_xor_sync(0xffffffffu, ps1, 1);
            ps1 += __shfl_xor_sync(0xffffffffu, ps1, 2);
            l0 = al0 * l0 + ps0;
            l1 = al1 * l1 + ps1;
            #pragma unroll
            for (int nt = 0; nt < 8; nt++) {
                o[nt][0] *= al0; o[nt][1] *= al0;
                o[nt][2] *= al1; o[nt][3] *= al1;
            }

            #pragma unroll
            for (int j = 0; j < 4; j++) {
                uint32_t vf[8][2];
                #pragma unroll
                for (int p = 0; p < 4; p++) {
                    uint32_t off = SWZ((uint32_t)((j*16 + v_row) * 128 + p*32 + v_db));
                    ldsm4t(vf[2*p][0], vf[2*p][1], vf[2*p+1][0], vf[2*p+1][1], sV + off);
                }
                #pragma unroll
                for (int nt = 0; nt < 8; nt++)
                    mma_fp(o[nt], pa[j], vf[nt]);
            }
        }
        __syncthreads();
        if (kt + 3 < ntiles) {
            load_kv(kvb + ((kt + 3) % 3) * ATSTG, khp, klp, vp, kt + 3, tid);
            CP_COMMIT();
        } else {
            CP_COMMIT();   // keep group count consistent with wait logic
        }
    }

    float rl0 = 1.f / l0, rl1 = 1.f / l1;
    size_t base0 = ((size_t)(b*TT + qr0) * CC) + h*64 + kc0;
    size_t base1 = base0 + (size_t)8 * CC;
    #pragma unroll
    for (int nt = 0; nt < 8; nt++) {
        *reinterpret_cast<__half2*>(y + base0 + nt*8) =
            __half2(__float2half(o[nt][0]*rl0), __float2half(o[nt][1]*rl0));
        *reinterpret_cast<__half2*>(y + base1 + nt*8) =
            __half2(__float2half(o[nt][2]*rl1), __float2half(o[nt][3]*rl1));
    }
}

// ================= launch =================
extern "C" void kernel_launch(void* const* d_in, const int* in_sizes, int n_in,
                              void* d_out, int out_size) {
    const float* x       = (const float*)d_in[0];
    const float* ln1_w   = (const float*)d_in[1];
    const float* ln1_b   = (const float*)d_in[2];
    const float* W_attn  = (const float*)d_in[3];
    const float* b_attn  = (const float*)d_in[4];
    const float* W_aproj = (const float*)d_in[5];
    const float* b_aproj = (const float*)d_in[6];
    const float* ln2_w   = (const float*)d_in[7];
    const float* ln2_b   = (const float*)d_in[8];
    const float* W_fc    = (const float*)d_in[9];
    const float* b_fc    = (const float*)d_in[10];
    const float* W_mproj = (const float*)d_in[11];
    const float* b_mproj = (const float*)d_in[12];
    float* out = (float*)d_out;

    float *x1, *mu, *inv;
    __half *y, *xth, *xtl, *qh, *ql, *kh, *kl, *v, *yh, *hh, *fch;
    __half *wah, *wal, *wap, *wfc, *wmp;
    cudaGetSymbolAddress((void**)&y,   g_y);
    cudaGetSymbolAddress((void**)&x1,  g_x1);
    cudaGetSymbolAddress((void**)&mu,  g_mu);
    cudaGetSymbolAddress((void**)&inv, g_inv);
    cudaGetSymbolAddress((void**)&xth, g_xt_h); cudaGetSymbolAddress((void**)&xtl, g_xt_l);
    cudaGetSymbolAddress((void**)&yh,  g_yh);
    cudaGetSymbolAddress((void**)&hh,  g_hh);
    cudaGetSymbolAddress((void**)&fch, g_fch);
    cudaGetSymbolAddress((void**)&qh, g_qh); cudaGetSymbolAddress((void**)&ql, g_ql);
    cudaGetSymbolAddress((void**)&kh, g_kh); cudaGetSymbolAddress((void**)&kl, g_kl);
    cudaGetSymbolAddress((void**)&v,  g_v);
    cudaGetSymbolAddress((void**)&wah, g_wattn_h); cudaGetSymbolAddress((void**)&wal, g_wattn_l);
    cudaGetSymbolAddress((void**)&wap, g_waproj);
    cudaGetSymbolAddress((void**)&wfc, g_wfc);
    cudaGetSymbolAddress((void**)&wmp, g_wmproj);

    cudaFuncSetAttribute(attn_hmma, cudaFuncAttributeMaxDynamicSharedMemorySize, AT_SMEM);
    cudaFuncSetAttribute(gemm_qkv, cudaFuncAttributeMaxDynamicSharedMemorySize, QGSMEM);
    cudaFuncSetAttribute(gemm_fp16<1>, cudaFuncAttributeMaxDynamicSharedMemorySize, F1SMEM);
    cudaFuncSetAttribute(gemm_fp16<2>, cudaFuncAttributeMaxDynamicSharedMemorySize, F1SMEM);

    // ---- forked-stream prologue (graph-capture compatible) ----
    cudaStream_t s2;
    cudaStreamCreateWithFlags(&s2, cudaStreamNonBlocking);
    cudaEvent_t evFork, evAttnW, evAprW, evJoin;
    cudaEventCreateWithFlags(&evFork,  cudaEventDisableTiming);
    cudaEventCreateWithFlags(&evAttnW, cudaEventDisableTiming);
    cudaEventCreateWithFlags(&evAprW,  cudaEventDisableTiming);
    cudaEventCreateWithFlags(&evJoin,  cudaEventDisableTiming);

    cudaEventRecord(evFork, 0);
    cudaStreamWaitEvent(s2, evFork, 0);

    dim3 tb(32, 8);
    wsplit_h_kernel<<<dim3(3*CC/32, CC/32), tb, 0, s2>>>(W_attn, wah, wal, CC, 3*CC);
    cudaEventRecord(evAttnW, s2);
    wtrans_h_kernel<<<dim3(CC/32,   CC/32), tb, 0, s2>>>(W_aproj, wap, CC,   CC);
    cudaEventRecord(evAprW, s2);
    wtrans_h_kernel<<<dim3(4*CC/32, CC/32), tb, 0, s2>>>(W_fc,    wfc, CC,   4*CC);
    wtrans_h_kernel<<<dim3(CC/32, 4*CC/32), tb, 0, s2>>>(W_mproj, wmp, 4*CC, CC);
    cudaEventRecord(evJoin, s2);

    // main stream
    logmap_fused<<<NROWS, 256>>>(x, ln1_w, ln1_b, xth, xtl, mu, inv);
    cudaStreamWaitEvent(0, evAttnW, 0);
    gemm_qkv<<<dim3(3*CC/128, NROWS/128), 256, QGSMEM>>>(
        xth, xtl, wah, wal, b_attn, qh, ql, kh, kl, v);
    attn_hmma<<<dim3(TT/128, BB*HH), 256, AT_SMEM>>>(qh, ql, kh, kl, v, y);
    expmap_fused<<<NROWS, 256>>>(x, ln1_w, ln1_b, y, yh, mu, inv);
    cudaStreamWaitEvent(0, evAprW, 0);
    gemm_fp16<1><<<dim3(CC/128, NROWS/128), 256, F1SMEM>>>(
        yh, wap, b_aproj, x, x1, nullptr, CC, CC);
    ln_half_kernel<<<NROWS, 256>>>(x1, ln2_w, ln2_b, hh);
    cudaStreamWaitEvent(0, evJoin, 0);
    gemm_fp16<2><<<dim3(4*CC/128, NROWS/128), 256, F1SMEM>>>(
        hh, wfc, b_fc, nullptr, nullptr, fch, 4*CC, CC);
    gemm_fp16<1><<<dim3(CC/128, NROWS/128), 256, F1SMEM>>>(
        fch, wmp, b_mproj, x1, out, nullptr, CC, 4*CC);
}

// round 16
// speedup vs baseline: 1.0156x; 1.0156x over previous
#include <cuda_runtime.h>
#include <cuda_fp16.h>
#include <math.h>
#include <stdint.h>

#define BB 2
#define TT 2048
#define CC 1024
#define HH 16
#define DH 64
#define NROWS (BB*TT)          // 4096

// ================= static scratch =================
__device__ __half g_y [NROWS*CC];       // attention output, fp16
__device__ float g_x1 [NROWS*CC];
__device__ float g_mu [NROWS];
__device__ float g_inv[NROWS];

__device__ __half g_xt_h[NROWS*CC], g_xt_l[NROWS*CC];
__device__ __half g_yh [NROWS*CC];
__device__ __half g_hh [NROWS*CC];
__device__ __half g_fch[NROWS*4*CC];

__device__ __half g_qh[NROWS*CC], g_ql[NROWS*CC];
__device__ __half g_kh[NROWS*CC], g_kl[NROWS*CC];
__device__ __half g_v [NROWS*CC];

__device__ __half g_wattn_h[3*CC*CC], g_wattn_l[3*CC*CC];
__device__ __half g_waproj[CC*CC];
__device__ __half g_wfc   [4*CC*CC];
__device__ __half g_wmproj[CC*4*CC];

#define QSCALE 0.18033688011112042f   // 0.125 * log2(e)

// ================= helpers =================
__device__ __forceinline__ uint32_t smem_u32(const void* p) {
    uint32_t a;
    asm("{ .reg .u64 t; cvta.to.shared.u64 t, %1; cvt.u32.u64 %0, t; }" : "=r"(a) : "l"(p));
    return a;
}
#define SWZ(x) ((x) ^ (((x) >> 3) & 0x70))

__device__ __forceinline__ void cp16(uint32_t sa, const void* g) {
    asm volatile("cp.async.cg.shared.global [%0], [%1], 16;" :: "r"(sa), "l"(g));
}
#define CP_COMMIT() asm volatile("cp.async.commit_group;" ::: "memory")
template <int N> __device__ __forceinline__ void cpwait() {
    asm volatile("cp.async.wait_group %0;" :: "n"(N) : "memory");
}

__device__ __forceinline__ void ldsm4(uint32_t& r0, uint32_t& r1, uint32_t& r2, uint32_t& r3, uint32_t a) {
    asm volatile("ldmatrix.sync.aligned.m8n8.x4.shared.b16 {%0,%1,%2,%3}, [%4];"
        : "=r"(r0), "=r"(r1), "=r"(r2), "=r"(r3) : "r"(a));
}
__device__ __forceinline__ void ldsm4t(uint32_t& r0, uint32_t& r1, uint32_t& r2, uint32_t& r3, uint32_t a) {
    asm volatile("ldmatrix.sync.aligned.m8n8.x4.trans.shared.b16 {%0,%1,%2,%3}, [%4];"
        : "=r"(r0), "=r"(r1), "=r"(r2), "=r"(r3) : "r"(a));
}
__device__ __forceinline__ void mma_fp(float* c, const uint32_t* a, const uint32_t* b) {
    asm volatile("mma.sync.aligned.m16n8k16.row.col.f32.f16.f16.f32 "
        "{%0,%1,%2,%3}, {%4,%5,%6,%7}, {%8,%9}, {%0,%1,%2,%3};"
        : "+f"(c[0]), "+f"(c[1]), "+f"(c[2]), "+f"(c[3])
        : "r"(a[0]), "r"(a[1]), "r"(a[2]), "r"(a[3]), "r"(b[0]), "r"(b[1]));
}
__device__ __forceinline__ float ex2f(float x) {
    float r; asm("ex2.approx.f32 %0, %1;" : "=f"(r) : "f"(x)); return r;
}
__device__ __forceinline__ void split2h(float v, __half& h, __half& l) {
    h = __float2half(v);
    l = __float2half(v - __half2float(h));
}
__device__ __forceinline__ uint32_t pack2h(__half a, __half b) {
    __half2 t(a, b); return *reinterpret_cast<uint32_t*>(&t);
}

// ================= block reduce (256 thr, up to 5 scalars) =================
__device__ __forceinline__ void block_reduce(float* vals, int n, float* scr) {
    int tid = threadIdx.x, lane = tid & 31, wid = tid >> 5;
    for (int k = 0; k < n; k++) {
        float v = vals[k];
        #pragma unroll
        for (int o = 16; o; o >>= 1) v += __shfl_xor_sync(0xffffffffu, v, o);
        if (lane == 0) scr[k*8 + wid] = v;
    }
    __syncthreads();
    if (tid == 0) {
        for (int k = 0; k < n; k++) {
            float s = 0.f;
            #pragma unroll
            for (int w = 0; w < 8; w++) s += scr[k*8 + w];
            scr[40 + k] = s;
        }
    }
    __syncthreads();
    for (int k = 0; k < n; k++) vals[k] = scr[40 + k];
    __syncthreads();
}

// ================= LayerNorm (fp16 out, row cached in smem) =================
__global__ void ln_half_kernel(const float* __restrict__ x, const float* __restrict__ w,
                               const float* __restrict__ b, __half* __restrict__ o) {
    __shared__ float scr[48];
    __shared__ float xr_s[CC];
    int row = blockIdx.x;
    const float* xr = x + (size_t)row * CC;
    int tid = threadIdx.x;
    float v2[2] = {0.f, 0.f};
    for (int i = tid; i < CC; i += 256) {
        float v = xr[i]; xr_s[i] = v;
        v2[0] += v; v2[1] += v*v;
    }
    block_reduce(v2, 2, scr);
    float mean = v2[0] * (1.0f/CC);
    float var  = v2[1] * (1.0f/CC) - mean*mean;
    float inv  = rsqrtf(var + 1e-5f);
    size_t base = (size_t)row * CC;
    for (int i = tid; i < CC; i += 256)
        o[base + i] = __float2half((xr_s[i] - mean) * inv * w[i] + b[i]);
}

// ================= fused LN1 + logmap -> fp16 pair; exports ref-row LN stats =================
__global__ void logmap_fused(const float* __restrict__ x,
                             const float* __restrict__ w, const float* __restrict__ b,
                             __half* __restrict__ oh, __half* __restrict__ ol,
                             float* __restrict__ mu_out, float* __restrict__ inv_out) {
    __shared__ float scr[48];
    __shared__ float un[CC], an[CC];
    int row = blockIdx.x;
    int t = row & (TT - 1);
    const float* xu = x + (size_t)row * CC;
    const float* xa = (t == 0) ? nullptr : xu - CC;
    int tid = threadIdx.x;

    float v4[4] = {0.f, 0.f, 0.f, 0.f};
    for (int i = tid; i < CC; i += 256) {
        float vu = xu[i]; un[i] = vu; v4[0] += vu; v4[1] += vu*vu;
        float va = xa ? xa[i] : 0.f;  an[i] = va;
        v4[2] += va; v4[3] += va*va;
    }
    block_reduce(v4, 4, scr);
    float mu_u = v4[0] * (1.0f/CC);
    float inv_u = rsqrtf(v4[1] * (1.0f/CC) - mu_u*mu_u + 1e-5f);
    float mu_a = v4[2] * (1.0f/CC);
    float inv_a = rsqrtf(fmaxf(v4[3] * (1.0f/CC) - mu_a*mu_a, 0.f) + 1e-5f);
    if (tid == 0) { mu_out[row] = mu_a; inv_out[row] = inv_a; }

    float v3[3] = {0.f, 0.f, 0.f};
    for (int i = tid; i < CC; i += 256) {
        float ui = (un[i] - mu_u) * inv_u * w[i] + b[i];
        float ai = xa ? ((an[i] - mu_a) * inv_a * w[i] + b[i]) : 0.f;
        un[i] = ui; an[i] = ai;
        v3[0] += ai*ai; v3[1] += ui*ui; v3[2] += ai*ui;
    }
    block_reduce(v3, 3, scr);
    float an2 = v3[0], un2 = v3[1], ipau = v3[2];

    float coefX = 1.f - 2.f*ipau + un2;
    float coefU = 1.f - an2;
    float rden  = 1.f / (1.f - 2.f*ipau + an2*un2);

    float mn2v[1] = {0.f};
    for (int i = tid; i < CC; i += 256) {
        float mi = (coefU * un[i] - coefX * an[i]) * rden;
        an[i] = mi;
        mn2v[0] += mi*mi;
    }
    block_reduce(mn2v, 1, scr);
    float mn = sqrtf(mn2v[0]);
    float cf = 1.f + an2;
    float arg = fminf(sqrtf(mn), 0.999f);
    float scale = cf * atanhf(arg) / mn;
    size_t base = (size_t)row * CC;
    for (int i = tid; i < CC; i += 256) {
        __half h, l; split2h(scale * an[i], h, l);
        oh[base + i] = h; ol[base + i] = l;
    }
}

// ================= fused LN1(row-1) + expmap (stats forwarded, y fp16) =================
__global__ void expmap_fused(const float* __restrict__ x,
                             const float* __restrict__ w, const float* __restrict__ b,
                             const __half* __restrict__ y, __half* __restrict__ o,
                             const float* __restrict__ mu_in, const float* __restrict__ inv_in) {
    __shared__ float scr[48];
    __shared__ float rf[CC], vv[CC];
    int row = blockIdx.x;
    int t = row & (TT - 1);
    const float* xa = (t == 0) ? nullptr : x + (size_t)(row - 1) * CC;
    const __half* v = y + (size_t)row * CC;
    int tid = threadIdx.x;

    float mu_a = mu_in[row], inv_a = inv_in[row];

    float v3[3] = {0.f, 0.f, 0.f};
    for (int i = tid; i < CC; i += 256) {
        float xi = xa ? ((xa[i] - mu_a) * inv_a * w[i] + b[i]) : 0.f;
        rf[i] = xi;
        float vi = __half2float(v[i]);
        vv[i] = vi;
        v3[0] += xi*xi; v3[1] += vi*vi; v3[2] += xi*vi;
    }
    block_reduce(v3, 3, scr);
    float refn2 = v3[0], vn2 = v3[1], xv = v3[2];

    float lam = 2.f / (1.f + refn2);
    float vn  = sqrtf(vn2);
    float th  = tanhf(sqrtf(lam * vn2 * 0.5f));
    float ss  = th / vn;
    float secn2 = th * th;
    float ipxs  = ss * xv;
    float coefX = 1.f + 2.f*ipxs + secn2;
    float coefY = (1.f - refn2) * ss;
    float rden  = 1.f / (1.f + 2.f*ipxs + refn2*secn2);
    size_t base = (size_t)row * CC;
    for (int i = tid; i < CC; i += 256)
        o[base + i] = __float2half((coefX * rf[i] + coefY * vv[i]) * rden);
}

// ================= weight transpose kernels =================
__global__ void wsplit_h_kernel(const float* __restrict__ W,
                                __half* __restrict__ Wh, __half* __restrict__ Wl,
                                int K, int N) {
    __shared__ float t[32][33];
    int n0 = blockIdx.x * 32, k0 = blockIdx.y * 32;
    int tx = threadIdx.x, ty = threadIdx.y;
    #pragma unroll
    for (int j = 0; j < 32; j += 8)
        t[ty + j][tx] = W[(size_t)(k0 + ty + j) * N + n0 + tx];
    __syncthreads();
    bool needs_lo = (n0 < 2*CC);   // V columns never read lo weights
    #pragma unroll
    for (int j = 0; j < 32; j += 8) {
        float v = t[tx][ty + j];
        __half h, l; split2h(v, h, l);
        size_t o = (size_t)(n0 + ty + j) * K + k0 + tx;
        Wh[o] = h;
        if (needs_lo) Wl[o] = l;
    }
}

__global__ void wtrans_h_kernel(const float* __restrict__ W, __half* __restrict__ Wt,
                                int K, int N) {
    __shared__ float t[32][33];
    int n0 = blockIdx.x * 32, k0 = blockIdx.y * 32;
    int tx = threadIdx.x, ty = threadIdx.y;
    #pragma unroll
    for (int j = 0; j < 32; j += 8)
        t[ty + j][tx] = W[(size_t)(k0 + ty + j) * N + n0 + tx];
    __syncthreads();
    #pragma unroll
    for (int j = 0; j < 32; j += 8)
        Wt[(size_t)(n0 + ty + j) * K + k0 + tx] = __float2half(t[tx][ty + j]);
}

// ================= shared tile loader (256 threads) =================
#define TILEB 16384
__device__ __forceinline__ void load_tile(uint32_t sdst, const void* gv,
                                          int row0, int Kd, int k0, int tid) {
    const __half* base = (const __half*)gv + (size_t)row0 * Kd + k0;
    #pragma unroll
    for (int i = 0; i < 4; i++) {
        int idx = tid * 4 + i;
        int r = idx >> 3, gc = idx & 7;
        uint32_t so = sdst + SWZ((uint32_t)(r * 128 + gc * 16));
        cp16(so, base + (size_t)r * Kd + gc * 8);
    }
}

// ================= QKV GEMM: 256 thr, 8 warps (2x4), warptile 64x32, 3-stage =================
// Per-tile pass policy:  Q cols (bn<CC): AhBh + AhBl (x2, Al skipped)
//                        K cols        : AhBh + AhBl + AlBh (x3)
//                        V cols        : AhBh (x1)
#define QSTAGEB (4*TILEB)
#define QGSMEM (3*QSTAGEB)

__global__ void __launch_bounds__(256, 1) gemm_qkv(
    const __half* __restrict__ Ah, const __half* __restrict__ Al,
    const __half* __restrict__ Bh, const __half* __restrict__ Bl,
    const float* __restrict__ bias,
    __half* __restrict__ Cqh, __half* __restrict__ Cql,
    __half* __restrict__ Ckh, __half* __restrict__ Ckl,
    __half* __restrict__ Cv)
{
    const int Kd = CC;
    extern __shared__ __align__(1024) char smem[];
    uint32_t sb = smem_u32(smem);
    int tid = threadIdx.x, wid = tid >> 5, lane = tid & 31;
    int wm = wid >> 2, wn = wid & 3;
    int bm = blockIdx.y * 128, bn = blockIdx.x * 128;
    const bool useBl = (bn < 2*CC);                 // Q and K tiles use weight-lo
    const bool useAl = (bn >= CC) && (bn < 2*CC);   // only K tiles use activation-lo

    float acc[4][4][4];
    #pragma unroll
    for (int mt = 0; mt < 4; mt++)
        #pragma unroll
        for (int nt = 0; nt < 4; nt++)
            #pragma unroll
            for (int r = 0; r < 4; r++) acc[mt][nt][r] = 0.f;

    const int nch = Kd >> 6;

    #pragma unroll
    for (int s = 0; s < 3; s++) {
        uint32_t st = sb + s * QSTAGEB;
        int k0 = s * 64;
        load_tile(st,           Ah, bm, Kd, k0, tid);
        load_tile(st + 2*TILEB, Bh, bn, Kd, k0, tid);
        if (useAl) load_tile(st +   TILEB, Al, bm, Kd, k0, tid);
        if (useBl) load_tile(st + 3*TILEB, Bl, bn, Kd, k0, tid);
        CP_COMMIT();
    }

    int grp = lane >> 3, rw = lane & 7;
    int a_row = (grp & 1) * 8 + rw;
    int a_kb  = (grp >> 1) * 16;
    int b_row = (grp >> 1) * 8 + rw;
    int b_kb  = (grp & 1) * 16;

    for (int c = 0; c < nch; c++) {
        int rem = nch - 1 - c;
        if (rem >= 2) cpwait<2>(); else if (rem == 1) cpwait<1>(); else cpwait<0>();
        __syncthreads();
        uint32_t st = sb + (c % 3) * QSTAGEB;
        uint32_t Ahs = st, Als = st + TILEB, Bhs = st + 2*TILEB, Bls = st + 3*TILEB;

        #pragma unroll
        for (int kk = 0; kk < 4; kk++) {
            uint32_t ah[4][4], al[4][4], bh[4][2], bl[4][2];
            #pragma unroll
            for (int mt = 0; mt < 4; mt++) {
                uint32_t off = SWZ((uint32_t)((wm*64 + mt*16 + a_row) * 128 + kk*32 + a_kb));
                ldsm4(ah[mt][0], ah[mt][1], ah[mt][2], ah[mt][3], Ahs + off);
                if (useAl) ldsm4(al[mt][0], al[mt][1], al[mt][2], al[mt][3], Als + off);
            }
            #pragma unroll
            for (int p = 0; p < 2; p++) {
                uint32_t off = SWZ((uint32_t)((wn*32 + p*16 + b_row) * 128 + kk*32 + b_kb));
                ldsm4(bh[2*p][0], bh[2*p][1], bh[2*p+1][0], bh[2*p+1][1], Bhs + off);
                if (useBl) ldsm4(bl[2*p][0], bl[2*p][1], bl[2*p+1][0], bl[2*p+1][1], Bls + off);
            }
            #pragma unroll
            for (int mt = 0; mt < 4; mt++)
                #pragma unroll
                for (int nt = 0; nt < 4; nt++) {
                    mma_fp(acc[mt][nt], ah[mt], bh[nt]);
                    if (useBl) mma_fp(acc[mt][nt], ah[mt], bl[nt]);
                    if (useAl) mma_fp(acc[mt][nt], al[mt], bh[nt]);
                }
        }
        __syncthreads();
        int cn = c + 3;
        if (cn < nch) {
            uint32_t sd = sb + (cn % 3) * QSTAGEB;
            int k0 = cn * 64;
            load_tile(sd,           Ah, bm, Kd, k0, tid);
            load_tile(sd + 2*TILEB, Bh, bn, Kd, k0, tid);
            if (useAl) load_tile(sd +   TILEB, Al, bm, Kd, k0, tid);
            if (useBl) load_tile(sd + 3*TILEB, Bl, bn, Kd, k0, tid);
            CP_COMMIT();
        }
    }

    int r0 = lane >> 2, c0 = (lane & 3) * 2;
    #pragma unroll
    for (int mt = 0; mt < 4; mt++) {
        #pragma unroll
        for (int nt = 0; nt < 4; nt++) {
            int col = bn + wn*32 + nt*8 + c0;
            float b0 = bias[col], b1 = bias[col + 1];
            int part = col >> 10;
            int head = (col >> 6) & 15;
            int d    = col & 63;
            #pragma unroll
            for (int half = 0; half < 2; half++) {
                int row = bm + wm*64 + mt*16 + r0 + half*8;
                float v0 = acc[mt][nt][half*2]     + b0;
                float v1 = acc[mt][nt][half*2 + 1] + b1;
                size_t off = ((((size_t)(row >> 11)) * 16 + head) * TT + (row & 2047)) * 64 + d;
                if (part == 2) {
                    *reinterpret_cast<__half2*>(Cv + off) =
                        __half2(__float2half(v0), __float2half(v1));
                } else {
                    if (part == 0) { v0 *= QSCALE; v1 *= QSCALE; }
                    __half h0, l0, h1, l1;
                    split2h(v0, h0, l0); split2h(v1, h1, l1);
                    __half* Dh = (part == 0) ? Cqh : Ckh;
                    __half* Dl = (part == 0) ? Cql : Ckl;
                    *reinterpret_cast<__half2*>(Dh + off) = __half2(h0, h1);
                    *reinterpret_cast<__half2*>(Dl + off) = __half2(l0, l1);
                }
            }
        }
    }
}

// ================= fp16 x1 GEMM: 256 thr, 8 warps (2x4), 2-stage =================
#define F1STAGE (2*TILEB)
#define F1SMEM (2*F1STAGE)

template<int EPI>
__global__ void __launch_bounds__(256, 2) gemm_fp16(
    const __half* __restrict__ A, const __half* __restrict__ B,
    const float* __restrict__ bias, const float* __restrict__ res,
    float* __restrict__ Cf, __half* __restrict__ Co,
    int Nd, int Kd)
{
    extern __shared__ __align__(1024) char smem[];
    uint32_t sb = smem_u32(smem);
    int tid = threadIdx.x, wid = tid >> 5, lane = tid & 31;
    int wm = wid >> 2, wn = wid & 3;
    int bm = blockIdx.y * 128, bn = blockIdx.x * 128;

    float acc[4][4][4];
    #pragma unroll
    for (int mt = 0; mt < 4; mt++)
        #pragma unroll
        for (int nt = 0; nt < 4; nt++)
            #pragma unroll
            for (int r = 0; r < 4; r++) acc[mt][nt][r] = 0.f;

    int nch = Kd >> 6;

    #pragma unroll
    for (int s = 0; s < 2; s++) {
        uint32_t st = sb + s * F1STAGE;
        int k0 = s * 64;
        load_tile(st,         A, bm, Kd, k0, tid);
        load_tile(st + TILEB, B, bn, Kd, k0, tid);
        CP_COMMIT();
    }

    int grp = lane >> 3, rw = lane & 7;
    int a_row = (grp & 1) * 8 + rw;
    int a_kb  = (grp >> 1) * 16;
    int b_row = (grp >> 1) * 8 + rw;
    int b_kb  = (grp & 1) * 16;

    for (int c = 0; c < nch; c++) {
        if (c + 1 < nch) cpwait<1>(); else cpwait<0>();
        __syncthreads();
        uint32_t st = sb + (c & 1) * F1STAGE;
        uint32_t As = st, Bs = st + TILEB;

        #pragma unroll
        for (int kk = 0; kk < 4; kk++) {
            uint32_t af[4][4], bf[4][2];
            #pragma unroll
            for (int mt = 0; mt < 4; mt++) {
                uint32_t off = SWZ((uint32_t)((wm*64 + mt*16 + a_row) * 128 + kk*32 + a_kb));
                ldsm4(af[mt][0], af[mt][1], af[mt][2], af[mt][3], As + off);
            }
            #pragma unroll
            for (int p = 0; p < 2; p++) {
                uint32_t off = SWZ((uint32_t)((wn*32 + p*16 + b_row) * 128 + kk*32 + b_kb));
                ldsm4(bf[2*p][0], bf[2*p][1], bf[2*p+1][0], bf[2*p+1][1], Bs + off);
            }
            #pragma unroll
            for (int mt = 0; mt < 4; mt++)
                #pragma unroll
                for (int nt = 0; nt < 4; nt++)
                    mma_fp(acc[mt][nt], af[mt], bf[nt]);
        }
        __syncthreads();
        int cn = c + 2;
        if (cn < nch) {
            int k0 = cn * 64;
            load_tile(st,         A, bm, Kd, k0, tid);
            load_tile(st + TILEB, B, bn, Kd, k0, tid);
            CP_COMMIT();
        }
    }

    int r0 = lane >> 2, c0 = (lane & 3) * 2;
    #pragma unroll
    for (int mt = 0; mt < 4; mt++) {
        #pragma unroll
        for (int nt = 0; nt < 4; nt++) {
            int col = bn + wn*32 + nt*8 + c0;
            float b0 = bias[col], b1 = bias[col + 1];
            #pragma unroll
            for (int half = 0; half < 2; half++) {
                int row = bm + wm*64 + mt*16 + r0 + half*8;
                float v0 = acc[mt][nt][half*2]     + b0;
                float v1 = acc[mt][nt][half*2 + 1] + b1;
                size_t off = (size_t)row * Nd + col;
                if (EPI == 2) {
                    v0 = v0 * normcdff(v0);
                    v1 = v1 * normcdff(v1);
                    *reinterpret_cast<__half2*>(Co + off) =
                        __half2(__float2half(v0), __float2half(v1));
                } else {
                    v0 += res[off]; v1 += res[off + 1];
                    *reinterpret_cast<float2*>(Cf + off) = make_float2(v0, v1);
                }
            }
        }
    }
}

// ================= flash attention: QK fp16x3, PV fp16x1, fp16 out, 2-stage KV =================
#define ATSTG 24576
#define AT_SMEM (32768 + 2*ATSTG)   // 81920

__device__ __forceinline__ void load_kv(uint32_t st,
        const __half* khp, const __half* klp,
        const __half* vp, int kt, int tid) {
    int k0 = kt * 64;
    #pragma unroll
    for (int i = 0; i < 2; i++) {
        int idx = tid * 2 + i;
        int r = idx >> 3, gc = idx & 7;
        uint32_t off = SWZ((uint32_t)(r * 128 + gc * 16));
        size_t g = (size_t)(k0 + r) * 64 + gc * 8;
        cp16(st + off,         khp + g);
        cp16(st + 8192 + off,  klp + g);
        cp16(st + 16384 + off, vp + g);
    }
}

__global__ void __launch_bounds__(256, 1) attn_hmma(
    const __half* __restrict__ Qh, const __half* __restrict__ Ql,
    const __half* __restrict__ Kh, const __half* __restrict__ Kl,
    const __half* __restrict__ V,
    __half* __restrict__ y)
{
    extern __shared__ __align__(1024) char smem[];
    uint32_t sb = smem_u32(smem);
    int tid = threadIdx.x, wid = tid >> 5, lane = tid & 31;
    int bhx = blockIdx.y, b = bhx >> 4, h = bhx & 15;
    int qblk = gridDim.x - 1 - blockIdx.x;
    int q0 = qblk * 128;
    size_t hb = (size_t)bhx * TT * DH;
    const __half *qhp = Qh + hb, *qlp = Ql + hb;
    const __half *khp = Kh + hb, *klp = Kl + hb;
    const __half *vp = V + hb;

    uint32_t sQh = sb, sQl = sb + 16384;
    uint32_t stg0 = sb + 32768, stg1 = sb + 32768 + ATSTG;

    int ntiles = 2 * (qblk + 1);

    load_tile(sQh, qhp, q0, 64, 0, tid);
    load_tile(sQl, qlp, q0, 64, 0, tid);
    load_kv(stg0, khp, klp, vp, 0, tid);
    CP_COMMIT();
    if (ntiles > 1) { load_kv(stg1, khp, klp, vp, 1, tid); CP_COMMIT(); }
    if (ntiles > 1) cpwait<1>(); else cpwait<0>();
    __syncthreads();

    int grp = lane >> 3, rw = lane & 7;
    int a_row = (grp & 1) * 8 + rw, a_kb = (grp >> 1) * 16;
    int b_row = (grp >> 1) * 8 + rw, b_kb = (grp & 1) * 16;
    int v_row = (grp & 1) * 8 + rw,  v_db = (grp >> 1) * 16;

    uint32_t qfh[4][4], qfl[4][4];
    #pragma unroll
    for (int kk = 0; kk < 4; kk++) {
        uint32_t off = SWZ((uint32_t)((wid*16 + a_row) * 128 + kk*32 + a_kb));
        ldsm4(qfh[kk][0], qfh[kk][1], qfh[kk][2], qfh[kk][3], sQh + off);
        ldsm4(qfl[kk][0], qfl[kk][1], qfl[kk][2], qfl[kk][3], sQl + off);
    }

    float o[8][4];
    #pragma unroll
    for (int nt = 0; nt < 8; nt++)
        #pragma unroll
        for (int r = 0; r < 4; r++) o[nt][r] = 0.f;
    float m0 = -1e30f, m1 = -1e30f, l0 = 0.f, l1 = 0.f;

    int qr0 = q0 + wid*16 + (lane >> 2);
    int kc0 = (lane & 3) * 2;

    for (int kt = 0; kt < ntiles; kt++) {
        if (kt > 0) {
            if (kt + 1 < ntiles) cpwait<1>(); else cpwait<0>();
            __syncthreads();
        }
        uint32_t st = (kt & 1) ? stg1 : stg0;
        int k0 = kt * 64;
        if (k0 <= q0 + wid*16 + 15) {
            uint32_t sKh = st, sKl = st + 8192, sV = st + 16384;
            float s[8][4];
            #pragma unroll
            for (int nt = 0; nt < 8; nt++)
                #pragma unroll
                for (int r = 0; r < 4; r++) s[nt][r] = 0.f;

            #pragma unroll
            for (int kk = 0; kk < 4; kk++) {
                uint32_t bhf[8][2], blf[8][2];
                #pragma unroll
                for (int p = 0; p < 4; p++) {
                    uint32_t off = SWZ((uint32_t)((p*16 + b_row) * 128 + kk*32 + b_kb));
                    ldsm4(bhf[2*p][0], bhf[2*p][1], bhf[2*p+1][0], bhf[2*p+1][1], sKh + off);
                    ldsm4(blf[2*p][0], blf[2*p][1], blf[2*p+1][0], blf[2*p+1][1], sKl + off);
                }
                #pragma unroll
                for (int nt = 0; nt < 8; nt++) {
                    mma_fp(s[nt], qfh[kk], bhf[nt]);
                    mma_fp(s[nt], qfh[kk], blf[nt]);
                    mma_fp(s[nt], qfl[kk], bhf[nt]);
                }
            }

            if (k0 + 63 > qr0) {
                #pragma unroll
                for (int nt = 0; nt < 8; nt++) {
                    int kg = k0 + nt*8 + kc0;
                    if (kg     > qr0)     s[nt][0] = -1e30f;
                    if (kg + 1 > qr0)     s[nt][1] = -1e30f;
                    if (kg     > qr0 + 8) s[nt][2] = -1e30f;
                    if (kg + 1 > qr0 + 8) s[nt][3] = -1e30f;
                }
            }

            float t0 = -1e30f, t1 = -1e30f;
            #pragma unroll
            for (int nt = 0; nt < 8; nt++) {
                t0 = fmaxf(t0, fmaxf(s[nt][0], s[nt][1]));
                t1 = fmaxf(t1, fmaxf(s[nt][2], s[nt][3]));
            }
            t0 = fmaxf(t0, __shfl_xor_sync(0xffffffffu, t0, 1));
            t0 = fmaxf(t0, __shfl_xor_sync(0xffffffffu, t0, 2));
            t1 = fmaxf(t1, __shfl_xor_sync(0xffffffffu, t1, 1));
            t1 = fmaxf(t1, __shfl_xor_sync(0xffffffffu, t1, 2));
            float mn0 = fmaxf(m0, t0), mn1 = fmaxf(m1, t1);
            float al0 = ex2f(m0 - mn0), al1 = ex2f(m1 - mn1);
            m0 = mn0; m1 = mn1;

            float ps0 = 0.f, ps1 = 0.f;
            uint32_t pa[4][4];
            #pragma unroll
            for (int nt = 0; nt < 8; nt++) {
                float p0 = ex2f(s[nt][0] - m0), p1 = ex2f(s[nt][1] - m0);
                float p2 = ex2f(s[nt][2] - m1), p3 = ex2f(s[nt][3] - m1);
                ps0 += p0 + p1; ps1 += p2 + p3;
                int jj = nt >> 1, rb = (nt & 1) * 2;
                pa[jj][rb]   = pack2h(__float2half(p0), __float2half(p1));
                pa[jj][rb+1] = pack2h(__float2half(p2), __float2half(p3));
            }
            ps0 += __shfl_xor_sync(0xffffffffu, ps0, 1);
            ps0 += __shfl_xor_sync(0xffffffffu, ps0, 2);
            ps1 += __shfl_xor_sync(0xffffffffu, ps1, 1);
            ps1 += __shfl_xor_sync(0xffffffffu, ps1, 2);
            l0 = al0 * l0 + ps0;
            l1 = al1 * l1 + ps1;
            #pragma unroll
            for (int nt = 0; nt < 8; nt++) {
                o[nt][0] *= al0; o[nt][1] *= al0;
                o[nt][2] *= al1; o[nt][3] *= al1;
            }

            #pragma unroll
            for (int j = 0; j < 4; j++) {
                uint32_t vf[8][2];
                #pragma unroll
                for (int p = 0; p < 4; p++) {
                    uint32_t off = SWZ((uint32_t)((j*16 + v_row) * 128 + p*32 + v_db));
                    ldsm4t(vf[2*p][0], vf[2*p][1], vf[2*p+1][0], vf[2*p+1][1], sV + off);
                }
                #pragma unroll
                for (int nt = 0; nt < 8; nt++)
                    mma_fp(o[nt], pa[j], vf[nt]);
            }
        }
        __syncthreads();
        if (kt + 2 < ntiles) {
            load_kv((kt & 1) ? stg1 : stg0, khp, klp, vp, kt + 2, tid);
            CP_COMMIT();
        }
    }

    float rl0 = 1.f / l0, rl1 = 1.f / l1;
    size_t base0 = ((size_t)(b*TT + qr0) * CC) + h*64 + kc0;
    size_t base1 = base0 + (size_t)8 * CC;
    #pragma unroll
    for (int nt = 0; nt < 8; nt++) {
        *reinterpret_cast<__half2*>(y + base0 + nt*8) =
            __half2(__float2half(o[nt][0]*rl0), __float2half(o[nt][1]*rl0));
        *reinterpret_cast<__half2*>(y + base1 + nt*8) =
            __half2(__float2half(o[nt][2]*rl1), __float2half(o[nt][3]*rl1));
    }
}

// ================= launch =================
extern "C" void kernel_launch(void* const* d_in, const int* in_sizes, int n_in,
                              void* d_out, int out_size) {
    const float* x       = (const float*)d_in[0];
    const float* ln1_w   = (const float*)d_in[1];
    const float* ln1_b   = (const float*)d_in[2];
    const float* W_attn  = (const float*)d_in[3];
    const float* b_attn  = (const float*)d_in[4];
    const float* W_aproj = (const float*)d_in[5];
    const float* b_aproj = (const float*)d_in[6];
    const float* ln2_w   = (const float*)d_in[7];
    const float* ln2_b   = (const float*)d_in[8];
    const float* W_fc    = (const float*)d_in[9];
    const float* b_fc    = (const float*)d_in[10];
    const float* W_mproj = (const float*)d_in[11];
    const float* b_mproj = (const float*)d_in[12];
    float* out = (float*)d_out;

    float *x1, *mu, *inv;
    __half *y, *xth, *xtl, *qh, *ql, *kh, *kl, *v, *yh, *hh, *fch;
    __half *wah, *wal, *wap, *wfc, *wmp;
    cudaGetSymbolAddress((void**)&y,   g_y);
    cudaGetSymbolAddress((void**)&x1,  g_x1);
    cudaGetSymbolAddress((void**)&mu,  g_mu);
    cudaGetSymbolAddress((void**)&inv, g_inv);
    cudaGetSymbolAddress((void**)&xth, g_xt_h); cudaGetSymbolAddress((void**)&xtl, g_xt_l);
    cudaGetSymbolAddress((void**)&yh,  g_yh);
    cudaGetSymbolAddress((void**)&hh,  g_hh);
    cudaGetSymbolAddress((void**)&fch, g_fch);
    cudaGetSymbolAddress((void**)&qh, g_qh); cudaGetSymbolAddress((void**)&ql, g_ql);
    cudaGetSymbolAddress((void**)&kh, g_kh); cudaGetSymbolAddress((void**)&kl, g_kl);
    cudaGetSymbolAddress((void**)&v,  g_v);
    cudaGetSymbolAddress((void**)&wah, g_wattn_h); cudaGetSymbolAddress((void**)&wal, g_wattn_l);
    cudaGetSymbolAddress((void**)&wap, g_waproj);
    cudaGetSymbolAddress((void**)&wfc, g_wfc);
    cudaGetSymbolAddress((void**)&wmp, g_wmproj);

    cudaFuncSetAttribute(attn_hmma, cudaFuncAttributeMaxDynamicSharedMemorySize, AT_SMEM);
    cudaFuncSetAttribute(gemm_qkv, cudaFuncAttributeMaxDynamicSharedMemorySize, QGSMEM);
    cudaFuncSetAttribute(gemm_fp16<1>, cudaFuncAttributeMaxDynamicSharedMemorySize, F1SMEM);
    cudaFuncSetAttribute(gemm_fp16<2>, cudaFuncAttributeMaxDynamicSharedMemorySize, F1SMEM);

    // ---- forked-stream prologue (graph-capture compatible) ----
    cudaStream_t s2;
    cudaStreamCreateWithFlags(&s2, cudaStreamNonBlocking);
    cudaEvent_t evFork, evAttnW, evAprW, evJoin;
    cudaEventCreateWithFlags(&evFork,  cudaEventDisableTiming);
    cudaEventCreateWithFlags(&evAttnW, cudaEventDisableTiming);
    cudaEventCreateWithFlags(&evAprW,  cudaEventDisableTiming);
    cudaEventCreateWithFlags(&evJoin,  cudaEventDisableTiming);

    cudaEventRecord(evFork, 0);
    cudaStreamWaitEvent(s2, evFork, 0);

    dim3 tb(32, 8);
    wsplit_h_kernel<<<dim3(3*CC/32, CC/32), tb, 0, s2>>>(W_attn, wah, wal, CC, 3*CC);
    cudaEventRecord(evAttnW, s2);
    wtrans_h_kernel<<<dim3(CC/32,   CC/32), tb, 0, s2>>>(W_aproj, wap, CC,   CC);
    cudaEventRecord(evAprW, s2);
    wtrans_h_kernel<<<dim3(4*CC/32, CC/32), tb, 0, s2>>>(W_fc,    wfc, CC,   4*CC);
    wtrans_h_kernel<<<dim3(CC/32, 4*CC/32), tb, 0, s2>>>(W_mproj, wmp, 4*CC, CC);
    cudaEventRecord(evJoin, s2);

    // main stream
    logmap_fused<<<NROWS, 256>>>(x, ln1_w, ln1_b, xth, xtl, mu, inv);
    cudaStreamWaitEvent(0, evAttnW, 0);
    gemm_qkv<<<dim3(3*CC/128, NROWS/128), 256, QGSMEM>>>(
        xth, xtl, wah, wal, b_attn, qh, ql, kh, kl, v);
    attn_hmma<<<dim3(TT/128, BB*HH), 256, AT_SMEM>>>(qh, ql, kh, kl, v, y);
    expmap_fused<<<NROWS, 256>>>(x, ln1_w, ln1_b, y, yh, mu, inv);
    cudaStreamWaitEvent(0, evAprW, 0);
    gemm_fp16<1><<<dim3(CC/128, NROWS/128), 256, F1SMEM>>>(
        yh, wap, b_aproj, x, x1, nullptr, CC, CC);
    ln_half_kernel<<<NROWS, 256>>>(x1, ln2_w, ln2_b, hh);
    cudaStreamWaitEvent(0, evJoin, 0);
    gemm_fp16<2><<<dim3(4*CC/128, NROWS/128), 256, F1SMEM>>>(
        hh, wfc, b_fc, nullptr, nullptr, fch, 4*CC, CC);
    gemm_fp16<1><<<dim3(CC/128, NROWS/128), 256, F1SMEM>>>(
        fch, wmp, b_mproj, x1, out, nullptr, CC, 4*CC);
}

// round 17
// speedup vs baseline: 1.0894x; 1.0727x over previous
#include <cuda_runtime.h>
#include <cuda_fp16.h>
#include <math.h>
#include <stdint.h>

#define BB 2
#define TT 2048
#define CC 1024
#define HH 16
#define DH 64
#define NROWS (BB*TT)          // 4096

// ================= static scratch =================
__device__ __half g_y [NROWS*CC];       // attention output, fp16
__device__ float g_x1 [NROWS*CC];
__device__ float g_mu [NROWS];
__device__ float g_inv[NROWS];

__device__ __half g_xt_h[NROWS*CC];
__device__ __half g_yh [NROWS*CC];
__device__ __half g_hh [NROWS*CC];
__device__ __half g_fch[NROWS*4*CC];

__device__ __half g_qh[NROWS*CC], g_ql[NROWS*CC];
__device__ __half g_kh[NROWS*CC], g_kl[NROWS*CC];
__device__ __half g_v [NROWS*CC];

__device__ __half g_wattn_h[3*CC*CC], g_wattn_l[3*CC*CC];
__device__ __half g_waproj[CC*CC];
__device__ __half g_wfc   [4*CC*CC];
__device__ __half g_wmproj[CC*4*CC];

#define QSCALE 0.18033688011112042f   // 0.125 * log2(e)

// ================= helpers =================
__device__ __forceinline__ uint32_t smem_u32(const void* p) {
    uint32_t a;
    asm("{ .reg .u64 t; cvta.to.shared.u64 t, %1; cvt.u32.u64 %0, t; }" : "=r"(a) : "l"(p));
    return a;
}
#define SWZ(x) ((x) ^ (((x) >> 3) & 0x70))

__device__ __forceinline__ void cp16(uint32_t sa, const void* g) {
    asm volatile("cp.async.cg.shared.global [%0], [%1], 16;" :: "r"(sa), "l"(g));
}
#define CP_COMMIT() asm volatile("cp.async.commit_group;" ::: "memory")
template <int N> __device__ __forceinline__ void cpwait() {
    asm volatile("cp.async.wait_group %0;" :: "n"(N) : "memory");
}

__device__ __forceinline__ void ldsm4(uint32_t& r0, uint32_t& r1, uint32_t& r2, uint32_t& r3, uint32_t a) {
    asm volatile("ldmatrix.sync.aligned.m8n8.x4.shared.b16 {%0,%1,%2,%3}, [%4];"
        : "=r"(r0), "=r"(r1), "=r"(r2), "=r"(r3) : "r"(a));
}
__device__ __forceinline__ void ldsm4t(uint32_t& r0, uint32_t& r1, uint32_t& r2, uint32_t& r3, uint32_t a) {
    asm volatile("ldmatrix.sync.aligned.m8n8.x4.trans.shared.b16 {%0,%1,%2,%3}, [%4];"
        : "=r"(r0), "=r"(r1), "=r"(r2), "=r"(r3) : "r"(a));
}
__device__ __forceinline__ void mma_fp(float* c, const uint32_t* a, const uint32_t* b) {
    asm volatile("mma.sync.aligned.m16n8k16.row.col.f32.f16.f16.f32 "
        "{%0,%1,%2,%3}, {%4,%5,%6,%7}, {%8,%9}, {%0,%1,%2,%3};"
        : "+f"(c[0]), "+f"(c[1]), "+f"(c[2]), "+f"(c[3])
        : "r"(a[0]), "r"(a[1]), "r"(a[2]), "r"(a[3]), "r"(b[0]), "r"(b[1]));
}
__device__ __forceinline__ float ex2f(float x) {
    float r; asm("ex2.approx.f32 %0, %1;" : "=f"(r) : "f"(x)); return r;
}
__device__ __forceinline__ void split2h(float v, __half& h, __half& l) {
    h = __float2half(v);
    l = __float2half(v - __half2float(h));
}
__device__ __forceinline__ uint32_t pack2h(__half a, __half b) {
    __half2 t(a, b); return *reinterpret_cast<uint32_t*>(&t);
}

// ================= block reduce (256 thr, up to 5 scalars) =================
__device__ __forceinline__ void block_reduce(float* vals, int n, float* scr) {
    int tid = threadIdx.x, lane = tid & 31, wid = tid >> 5;
    for (int k = 0; k < n; k++) {
        float v = vals[k];
        #pragma unroll
        for (int o = 16; o; o >>= 1) v += __shfl_xor_sync(0xffffffffu, v, o);
        if (lane == 0) scr[k*8 + wid] = v;
    }
    __syncthreads();
    if (tid == 0) {
        for (int k = 0; k < n; k++) {
            float s = 0.f;
            #pragma unroll
            for (int w = 0; w < 8; w++) s += scr[k*8 + w];
            scr[40 + k] = s;
        }
    }
    __syncthreads();
    for (int k = 0; k < n; k++) vals[k] = scr[40 + k];
    __syncthreads();
}

// ================= LayerNorm (fp16 out, row cached in smem) =================
__global__ void ln_half_kernel(const float* __restrict__ x, const float* __restrict__ w,
                               const float* __restrict__ b, __half* __restrict__ o) {
    __shared__ float scr[48];
    __shared__ float xr_s[CC];
    int row = blockIdx.x;
    const float* xr = x + (size_t)row * CC;
    int tid = threadIdx.x;
    float v2[2] = {0.f, 0.f};
    for (int i = tid; i < CC; i += 256) {
        float v = xr[i]; xr_s[i] = v;
        v2[0] += v; v2[1] += v*v;
    }
    block_reduce(v2, 2, scr);
    float mean = v2[0] * (1.0f/CC);
    float var  = v2[1] * (1.0f/CC) - mean*mean;
    float inv  = rsqrtf(var + 1e-5f);
    size_t base = (size_t)row * CC;
    for (int i = tid; i < CC; i += 256)
        o[base + i] = __float2half((xr_s[i] - mean) * inv * w[i] + b[i]);
}

// ================= fused LN1 + logmap -> fp16 (hi only); exports ref-row LN stats =================
__global__ void logmap_fused(const float* __restrict__ x,
                             const float* __restrict__ w, const float* __restrict__ b,
                             __half* __restrict__ oh,
                             float* __restrict__ mu_out, float* __restrict__ inv_out) {
    __shared__ float scr[48];
    __shared__ float un[CC], an[CC];
    int row = blockIdx.x;
    int t = row & (TT - 1);
    const float* xu = x + (size_t)row * CC;
    const float* xa = (t == 0) ? nullptr : xu - CC;
    int tid = threadIdx.x;

    float v4[4] = {0.f, 0.f, 0.f, 0.f};
    for (int i = tid; i < CC; i += 256) {
        float vu = xu[i]; un[i] = vu; v4[0] += vu; v4[1] += vu*vu;
        float va = xa ? xa[i] : 0.f;  an[i] = va;
        v4[2] += va; v4[3] += va*va;
    }
    block_reduce(v4, 4, scr);
    float mu_u = v4[0] * (1.0f/CC);
    float inv_u = rsqrtf(v4[1] * (1.0f/CC) - mu_u*mu_u + 1e-5f);
    float mu_a = v4[2] * (1.0f/CC);
    float inv_a = rsqrtf(fmaxf(v4[3] * (1.0f/CC) - mu_a*mu_a, 0.f) + 1e-5f);
    if (tid == 0) { mu_out[row] = mu_a; inv_out[row] = inv_a; }

    float v3[3] = {0.f, 0.f, 0.f};
    for (int i = tid; i < CC; i += 256) {
        float ui = (un[i] - mu_u) * inv_u * w[i] + b[i];
        float ai = xa ? ((an[i] - mu_a) * inv_a * w[i] + b[i]) : 0.f;
        un[i] = ui; an[i] = ai;
        v3[0] += ai*ai; v3[1] += ui*ui; v3[2] += ai*ui;
    }
    block_reduce(v3, 3, scr);
    float an2 = v3[0], un2 = v3[1], ipau = v3[2];

    float coefX = 1.f - 2.f*ipau + un2;
    float coefU = 1.f - an2;
    float rden  = 1.f / (1.f - 2.f*ipau + an2*un2);

    float mn2v[1] = {0.f};
    for (int i = tid; i < CC; i += 256) {
        float mi = (coefU * un[i] - coefX * an[i]) * rden;
        an[i] = mi;
        mn2v[0] += mi*mi;
    }
    block_reduce(mn2v, 1, scr);
    float mn = sqrtf(mn2v[0]);
    float cf = 1.f + an2;
    float arg = fminf(sqrtf(mn), 0.999f);
    float scale = cf * atanhf(arg) / mn;
    size_t base = (size_t)row * CC;
    for (int i = tid; i < CC; i += 256)
        oh[base + i] = __float2half(scale * an[i]);
}

// ================= fused LN1(row-1) + expmap (stats forwarded, y fp16) =================
__global__ void expmap_fused(const float* __restrict__ x,
                             const float* __restrict__ w, const float* __restrict__ b,
                             const __half* __restrict__ y, __half* __restrict__ o,
                             const float* __restrict__ mu_in, const float* __restrict__ inv_in) {
    __shared__ float scr[48];
    __shared__ float rf[CC], vv[CC];
    int row = blockIdx.x;
    int t = row & (TT - 1);
    const float* xa = (t == 0) ? nullptr : x + (size_t)(row - 1) * CC;
    const __half* v = y + (size_t)row * CC;
    int tid = threadIdx.x;

    float mu_a = mu_in[row], inv_a = inv_in[row];

    float v3[3] = {0.f, 0.f, 0.f};
    for (int i = tid; i < CC; i += 256) {
        float xi = xa ? ((xa[i] - mu_a) * inv_a * w[i] + b[i]) : 0.f;
        rf[i] = xi;
        float vi = __half2float(v[i]);
        vv[i] = vi;
        v3[0] += xi*xi; v3[1] += vi*vi; v3[2] += xi*vi;
    }
    block_reduce(v3, 3, scr);
    float refn2 = v3[0], vn2 = v3[1], xv = v3[2];

    float lam = 2.f / (1.f + refn2);
    float vn  = sqrtf(vn2);
    float th  = tanhf(sqrtf(lam * vn2 * 0.5f));
    float ss  = th / vn;
    float secn2 = th * th;
    float ipxs  = ss * xv;
    float coefX = 1.f + 2.f*ipxs + secn2;
    float coefY = (1.f - refn2) * ss;
    float rden  = 1.f / (1.f + 2.f*ipxs + refn2*secn2);
    size_t base = (size_t)row * CC;
    for (int i = tid; i < CC; i += 256)
        o[base + i] = __float2half((coefX * rf[i] + coefY * vv[i]) * rden);
}

// ================= weight transpose kernels =================
__global__ void wsplit_h_kernel(const float* __restrict__ W,
                                __half* __restrict__ Wh, __half* __restrict__ Wl,
                                int K, int N) {
    __shared__ float t[32][33];
    int n0 = blockIdx.x * 32, k0 = blockIdx.y * 32;
    int tx = threadIdx.x, ty = threadIdx.y;
    #pragma unroll
    for (int j = 0; j < 32; j += 8)
        t[ty + j][tx] = W[(size_t)(k0 + ty + j) * N + n0 + tx];
    __syncthreads();
    bool needs_lo = (n0 < 2*CC);   // V columns never read lo weights
    #pragma unroll
    for (int j = 0; j < 32; j += 8) {
        float v = t[tx][ty + j];
        __half h, l; split2h(v, h, l);
        size_t o = (size_t)(n0 + ty + j) * K + k0 + tx;
        Wh[o] = h;
        if (needs_lo) Wl[o] = l;
    }
}

__global__ void wtrans_h_kernel(const float* __restrict__ W, __half* __restrict__ Wt,
                                int K, int N) {
    __shared__ float t[32][33];
    int n0 = blockIdx.x * 32, k0 = blockIdx.y * 32;
    int tx = threadIdx.x, ty = threadIdx.y;
    #pragma unroll
    for (int j = 0; j < 32; j += 8)
        t[ty + j][tx] = W[(size_t)(k0 + ty + j) * N + n0 + tx];
    __syncthreads();
    #pragma unroll
    for (int j = 0; j < 32; j += 8)
        Wt[(size_t)(n0 + ty + j) * K + k0 + tx] = __float2half(t[tx][ty + j]);
}

// ================= shared tile loader (256 threads) =================
#define TILEB 16384
__device__ __forceinline__ void load_tile(uint32_t sdst, const void* gv,
                                          int row0, int Kd, int k0, int tid) {
    const __half* base = (const __half*)gv + (size_t)row0 * Kd + k0;
    #pragma unroll
    for (int i = 0; i < 4; i++) {
        int idx = tid * 4 + i;
        int r = idx >> 3, gc = idx & 7;
        uint32_t so = sdst + SWZ((uint32_t)(r * 128 + gc * 16));
        cp16(so, base + (size_t)r * Kd + gc * 8);
    }
}

// ================= QKV GEMM: 256 thr, 8 warps (2x4), warptile 64x32, 3-stage =================
// Per-tile pass policy:  Q/K cols (bn<2CC): AhBh + AhBl (x2)
//                        V cols           : AhBh (x1)
#define QSTAGEB (3*TILEB)     // Ah, Bh, Bl
#define QGSMEM (3*QSTAGEB)    // 147456

__global__ void __launch_bounds__(256, 1) gemm_qkv(
    const __half* __restrict__ Ah,
    const __half* __restrict__ Bh, const __half* __restrict__ Bl,
    const float* __restrict__ bias,
    __half* __restrict__ Cqh, __half* __restrict__ Cql,
    __half* __restrict__ Ckh, __half* __restrict__ Ckl,
    __half* __restrict__ Cv)
{
    const int Kd = CC;
    extern __shared__ __align__(1024) char smem[];
    uint32_t sb = smem_u32(smem);
    int tid = threadIdx.x, wid = tid >> 5, lane = tid & 31;
    int wm = wid >> 2, wn = wid & 3;
    int bm = blockIdx.y * 128, bn = blockIdx.x * 128;
    const bool useBl = (bn < 2*CC);    // Q and K tiles use weight-lo

    float acc[4][4][4];
    #pragma unroll
    for (int mt = 0; mt < 4; mt++)
        #pragma unroll
        for (int nt = 0; nt < 4; nt++)
            #pragma unroll
            for (int r = 0; r < 4; r++) acc[mt][nt][r] = 0.f;

    const int nch = Kd >> 6;

    #pragma unroll
    for (int s = 0; s < 3; s++) {
        uint32_t st = sb + s * QSTAGEB;
        int k0 = s * 64;
        load_tile(st,           Ah, bm, Kd, k0, tid);
        load_tile(st +   TILEB, Bh, bn, Kd, k0, tid);
        if (useBl) load_tile(st + 2*TILEB, Bl, bn, Kd, k0, tid);
        CP_COMMIT();
    }

    int grp = lane >> 3, rw = lane & 7;
    int a_row = (grp & 1) * 8 + rw;
    int a_kb  = (grp >> 1) * 16;
    int b_row = (grp >> 1) * 8 + rw;
    int b_kb  = (grp & 1) * 16;

    for (int c = 0; c < nch; c++) {
        int rem = nch - 1 - c;
        if (rem >= 2) cpwait<2>(); else if (rem == 1) cpwait<1>(); else cpwait<0>();
        __syncthreads();
        uint32_t st = sb + (c % 3) * QSTAGEB;
        uint32_t Ahs = st, Bhs = st + TILEB, Bls = st + 2*TILEB;

        #pragma unroll
        for (int kk = 0; kk < 4; kk++) {
            uint32_t ah[4][4], bh[4][2], bl[4][2];
            #pragma unroll
            for (int mt = 0; mt < 4; mt++) {
                uint32_t off = SWZ((uint32_t)((wm*64 + mt*16 + a_row) * 128 + kk*32 + a_kb));
                ldsm4(ah[mt][0], ah[mt][1], ah[mt][2], ah[mt][3], Ahs + off);
            }
            #pragma unroll
            for (int p = 0; p < 2; p++) {
                uint32_t off = SWZ((uint32_t)((wn*32 + p*16 + b_row) * 128 + kk*32 + b_kb));
                ldsm4(bh[2*p][0], bh[2*p][1], bh[2*p+1][0], bh[2*p+1][1], Bhs + off);
                if (useBl) ldsm4(bl[2*p][0], bl[2*p][1], bl[2*p+1][0], bl[2*p+1][1], Bls + off);
            }
            #pragma unroll
            for (int mt = 0; mt < 4; mt++)
                #pragma unroll
                for (int nt = 0; nt < 4; nt++) {
                    mma_fp(acc[mt][nt], ah[mt], bh[nt]);
                    if (useBl) mma_fp(acc[mt][nt], ah[mt], bl[nt]);
                }
        }
        __syncthreads();
        int cn = c + 3;
        if (cn < nch) {
            uint32_t sd = sb + (cn % 3) * QSTAGEB;
            int k0 = cn * 64;
            load_tile(sd,           Ah, bm, Kd, k0, tid);
            load_tile(sd +   TILEB, Bh, bn, Kd, k0, tid);
            if (useBl) load_tile(sd + 2*TILEB, Bl, bn, Kd, k0, tid);
            CP_COMMIT();
        }
    }

    int r0 = lane >> 2, c0 = (lane & 3) * 2;
    #pragma unroll
    for (int mt = 0; mt < 4; mt++) {
        #pragma unroll
        for (int nt = 0; nt < 4; nt++) {
            int col = bn + wn*32 + nt*8 + c0;
            float b0 = bias[col], b1 = bias[col + 1];
            int part = col >> 10;
            int head = (col >> 6) & 15;
            int d    = col & 63;
            #pragma unroll
            for (int half = 0; half < 2; half++) {
                int row = bm + wm*64 + mt*16 + r0 + half*8;
                float v0 = acc[mt][nt][half*2]     + b0;
                float v1 = acc[mt][nt][half*2 + 1] + b1;
                size_t off = ((((size_t)(row >> 11)) * 16 + head) * TT + (row & 2047)) * 64 + d;
                if (part == 2) {
                    *reinterpret_cast<__half2*>(Cv + off) =
                        __half2(__float2half(v0), __float2half(v1));
                } else {
                    if (part == 0) { v0 *= QSCALE; v1 *= QSCALE; }
                    __half h0, l0, h1, l1;
                    split2h(v0, h0, l0); split2h(v1, h1, l1);
                    __half* Dh = (part == 0) ? Cqh : Ckh;
                    __half* Dl = (part == 0) ? Cql : Ckl;
                    *reinterpret_cast<__half2*>(Dh + off) = __half2(h0, h1);
                    *reinterpret_cast<__half2*>(Dl + off) = __half2(l0, l1);
                }
            }
        }
    }
}

// ================= fp16 x1 GEMM: 256 thr, 8 warps (2x4), 2-stage =================
#define F1STAGE (2*TILEB)
#define F1SMEM (2*F1STAGE)

template<int EPI>
__global__ void __launch_bounds__(256, 2) gemm_fp16(
    const __half* __restrict__ A, const __half* __restrict__ B,
    const float* __restrict__ bias, const float* __restrict__ res,
    float* __restrict__ Cf, __half* __restrict__ Co,
    int Nd, int Kd)
{
    extern __shared__ __align__(1024) char smem[];
    uint32_t sb = smem_u32(smem);
    int tid = threadIdx.x, wid = tid >> 5, lane = tid & 31;
    int wm = wid >> 2, wn = wid & 3;
    int bm = blockIdx.y * 128, bn = blockIdx.x * 128;

    float acc[4][4][4];
    #pragma unroll
    for (int mt = 0; mt < 4; mt++)
        #pragma unroll
        for (int nt = 0; nt < 4; nt++)
            #pragma unroll
            for (int r = 0; r < 4; r++) acc[mt][nt][r] = 0.f;

    int nch = Kd >> 6;

    #pragma unroll
    for (int s = 0; s < 2; s++) {
        uint32_t st = sb + s * F1STAGE;
        int k0 = s * 64;
        load_tile(st,         A, bm, Kd, k0, tid);
        load_tile(st + TILEB, B, bn, Kd, k0, tid);
        CP_COMMIT();
    }

    int grp = lane >> 3, rw = lane & 7;
    int a_row = (grp & 1) * 8 + rw;
    int a_kb  = (grp >> 1) * 16;
    int b_row = (grp >> 1) * 8 + rw;
    int b_kb  = (grp & 1) * 16;

    for (int c = 0; c < nch; c++) {
        if (c + 1 < nch) cpwait<1>(); else cpwait<0>();
        __syncthreads();
        uint32_t st = sb + (c & 1) * F1STAGE;
        uint32_t As = st, Bs = st + TILEB;

        #pragma unroll
        for (int kk = 0; kk < 4; kk++) {
            uint32_t af[4][4], bf[4][2];
            #pragma unroll
            for (int mt = 0; mt < 4; mt++) {
                uint32_t off = SWZ((uint32_t)((wm*64 + mt*16 + a_row) * 128 + kk*32 + a_kb));
                ldsm4(af[mt][0], af[mt][1], af[mt][2], af[mt][3], As + off);
            }
            #pragma unroll
            for (int p = 0; p < 2; p++) {
                uint32_t off = SWZ((uint32_t)((wn*32 + p*16 + b_row) * 128 + kk*32 + b_kb));
                ldsm4(bf[2*p][0], bf[2*p][1], bf[2*p+1][0], bf[2*p+1][1], Bs + off);
            }
            #pragma unroll
            for (int mt = 0; mt < 4; mt++)
                #pragma unroll
                for (int nt = 0; nt < 4; nt++)
                    mma_fp(acc[mt][nt], af[mt], bf[nt]);
        }
        __syncthreads();
        int cn = c + 2;
        if (cn < nch) {
            int k0 = cn * 64;
            load_tile(st,         A, bm, Kd, k0, tid);
            load_tile(st + TILEB, B, bn, Kd, k0, tid);
            CP_COMMIT();
        }
    }

    int r0 = lane >> 2, c0 = (lane & 3) * 2;
    #pragma unroll
    for (int mt = 0; mt < 4; mt++) {
        #pragma unroll
        for (int nt = 0; nt < 4; nt++) {
            int col = bn + wn*32 + nt*8 + c0;
            float b0 = bias[col], b1 = bias[col + 1];
            #pragma unroll
            for (int half = 0; half < 2; half++) {
                int row = bm + wm*64 + mt*16 + r0 + half*8;
                float v0 = acc[mt][nt][half*2]     + b0;
                float v1 = acc[mt][nt][half*2 + 1] + b1;
                size_t off = (size_t)row * Nd + col;
                if (EPI == 2) {
                    v0 = v0 * normcdff(v0);
                    v1 = v1 * normcdff(v1);
                    *reinterpret_cast<__half2*>(Co + off) =
                        __half2(__float2half(v0), __float2half(v1));
                } else {
                    v0 += res[off]; v1 += res[off + 1];
                    *reinterpret_cast<float2*>(Cf + off) = make_float2(v0, v1);
                }
            }
        }
    }
}

// ================= flash attention: QK fp16x3, PV fp16x1, fp16 out, 2-stage KV =================
#define ATSTG 24576
#define AT_SMEM (32768 + 2*ATSTG)   // 81920

__device__ __forceinline__ void load_kv(uint32_t st,
        const __half* khp, const __half* klp,
        const __half* vp, int kt, int tid) {
    int k0 = kt * 64;
    #pragma unroll
    for (int i = 0; i < 2; i++) {
        int idx = tid * 2 + i;
        int r = idx >> 3, gc = idx & 7;
        uint32_t off = SWZ((uint32_t)(r * 128 + gc * 16));
        size_t g = (size_t)(k0 + r) * 64 + gc * 8;
        cp16(st + off,         khp + g);
        cp16(st + 8192 + off,  klp + g);
        cp16(st + 16384 + off, vp + g);
    }
}

__global__ void __launch_bounds__(256, 1) attn_hmma(
    const __half* __restrict__ Qh, const __half* __restrict__ Ql,
    const __half* __restrict__ Kh, const __half* __restrict__ Kl,
    const __half* __restrict__ V,
    __half* __restrict__ y)
{
    extern __shared__ __align__(1024) char smem[];
    uint32_t sb = smem_u32(smem);
    int tid = threadIdx.x, wid = tid >> 5, lane = tid & 31;
    int bhx = blockIdx.y, b = bhx >> 4, h = bhx & 15;
    int qblk = gridDim.x - 1 - blockIdx.x;
    int q0 = qblk * 128;
    size_t hb = (size_t)bhx * TT * DH;
    const __half *qhp = Qh + hb, *qlp = Ql + hb;
    const __half *khp = Kh + hb, *klp = Kl + hb;
    const __half *vp = V + hb;

    uint32_t sQh = sb, sQl = sb + 16384;
    uint32_t stg0 = sb + 32768, stg1 = sb + 32768 + ATSTG;

    int ntiles = 2 * (qblk + 1);

    load_tile(sQh, qhp, q0, 64, 0, tid);
    load_tile(sQl, qlp, q0, 64, 0, tid);
    load_kv(stg0, khp, klp, vp, 0, tid);
    CP_COMMIT();
    if (ntiles > 1) { load_kv(stg1, khp, klp, vp, 1, tid); CP_COMMIT(); }
    if (ntiles > 1) cpwait<1>(); else cpwait<0>();
    __syncthreads();

    int grp = lane >> 3, rw = lane & 7;
    int a_row = (grp & 1) * 8 + rw, a_kb = (grp >> 1) * 16;
    int b_row = (grp >> 1) * 8 + rw, b_kb = (grp & 1) * 16;
    int v_row = (grp & 1) * 8 + rw,  v_db = (grp >> 1) * 16;

    uint32_t qfh[4][4], qfl[4][4];
    #pragma unroll
    for (int kk = 0; kk < 4; kk++) {
        uint32_t off = SWZ((uint32_t)((wid*16 + a_row) * 128 + kk*32 + a_kb));
        ldsm4(qfh[kk][0], qfh[kk][1], qfh[kk][2], qfh[kk][3], sQh + off);
        ldsm4(qfl[kk][0], qfl[kk][1], qfl[kk][2], qfl[kk][3], sQl + off);
    }

    float o[8][4];
    #pragma unroll
    for (int nt = 0; nt < 8; nt++)
        #pragma unroll
        for (int r = 0; r < 4; r++) o[nt][r] = 0.f;
    float m0 = -1e30f, m1 = -1e30f, l0 = 0.f, l1 = 0.f;

    int qr0 = q0 + wid*16 + (lane >> 2);
    int kc0 = (lane & 3) * 2;

    for (int kt = 0; kt < ntiles; kt++) {
        if (kt > 0) {
            if (kt + 1 < ntiles) cpwait<1>(); else cpwait<0>();
            __syncthreads();
        }
        uint32_t st = (kt & 1) ? stg1 : stg0;
        int k0 = kt * 64;
        if (k0 <= q0 + wid*16 + 15) {
            uint32_t sKh = st, sKl = st + 8192, sV = st + 16384;
            float s[8][4];
            #pragma unroll
            for (int nt = 0; nt < 8; nt++)
                #pragma unroll
                for (int r = 0; r < 4; r++) s[nt][r] = 0.f;

            #pragma unroll
            for (int kk = 0; kk < 4; kk++) {
                uint32_t bhf[8][2], blf[8][2];
                #pragma unroll
                for (int p = 0; p < 4; p++) {
                    uint32_t off = SWZ((uint32_t)((p*16 + b_row) * 128 + kk*32 + b_kb));
                    ldsm4(bhf[2*p][0], bhf[2*p][1], bhf[2*p+1][0], bhf[2*p+1][1], sKh + off);
                    ldsm4(blf[2*p][0], blf[2*p][1], blf[2*p+1][0], blf[2*p+1][1], sKl + off);
                }
                #pragma unroll
                for (int nt = 0; nt < 8; nt++) {
                    mma_fp(s[nt], qfh[kk], bhf[nt]);
                    mma_fp(s[nt], qfh[kk], blf[nt]);
                    mma_fp(s[nt], qfl[kk], bhf[nt]);
                }
            }

            if (k0 + 63 > qr0) {
                #pragma unroll
                for (int nt = 0; nt < 8; nt++) {
                    int kg = k0 + nt*8 + kc0;
                    if (kg     > qr0)     s[nt][0] = -1e30f;
                    if (kg + 1 > qr0)     s[nt][1] = -1e30f;
                    if (kg     > qr0 + 8) s[nt][2] = -1e30f;
                    if (kg + 1 > qr0 + 8) s[nt][3] = -1e30f;
                }
            }

            float t0 = -1e30f, t1 = -1e30f;
            #pragma unroll
            for (int nt = 0; nt < 8; nt++) {
                t0 = fmaxf(t0, fmaxf(s[nt][0], s[nt][1]));
                t1 = fmaxf(t1, fmaxf(s[nt][2], s[nt][3]));
            }
            t0 = fmaxf(t0, __shfl_xor_sync(0xffffffffu, t0, 1));
            t0 = fmaxf(t0, __shfl_xor_sync(0xffffffffu, t0, 2));
            t1 = fmaxf(t1, __shfl_xor_sync(0xffffffffu, t1, 1));
            t1 = fmaxf(t1, __shfl_xor_sync(0xffffffffu, t1, 2));
            float mn0 = fmaxf(m0, t0), mn1 = fmaxf(m1, t1);
            float al0 = ex2f(m0 - mn0), al1 = ex2f(m1 - mn1);
            m0 = mn0; m1 = mn1;

            float ps0 = 0.f, ps1 = 0.f;
            uint32_t pa[4][4];
            #pragma unroll
            for (int nt = 0; nt < 8; nt++) {
                float p0 = ex2f(s[nt][0] - m0), p1 = ex2f(s[nt][1] - m0);
                float p2 = ex2f(s[nt][2] - m1), p3 = ex2f(s[nt][3] - m1);
                ps0 += p0 + p1; ps1 += p2 + p3;
                int jj = nt >> 1, rb = (nt & 1) * 2;
                pa[jj][rb]   = pack2h(__float2half(p0), __float2half(p1));
                pa[jj][rb+1] = pack2h(__float2half(p2), __float2half(p3));
            }
            ps0 += __shfl_xor_sync(0xffffffffu, ps0, 1);
            ps0 += __shfl_xor_sync(0xffffffffu, ps0, 2);
            ps1 += __shfl_xor_sync(0xffffffffu, ps1, 1);
            ps1 += __shfl_xor_sync(0xffffffffu, ps1, 2);
            l0 = al0 * l0 + ps0;
            l1 = al1 * l1 + ps1;
            #pragma unroll
            for (int nt = 0; nt < 8; nt++) {
                o[nt][0] *= al0; o[nt][1] *= al0;
                o[nt][2] *= al1; o[nt][3] *= al1;
            }

            #pragma unroll
            for (int j = 0; j < 4; j++) {
                uint32_t vf[8][2];
                #pragma unroll
                for (int p = 0; p < 4; p++) {
                    uint32_t off = SWZ((uint32_t)((j*16 + v_row) * 128 + p*32 + v_db));
                    ldsm4t(vf[2*p][0], vf[2*p][1], vf[2*p+1][0], vf[2*p+1][1], sV + off);
                }
                #pragma unroll
                for (int nt = 0; nt < 8; nt++)
                    mma_fp(o[nt], pa[j], vf[nt]);
            }
        }
        __syncthreads();
        if (kt + 2 < ntiles) {
            load_kv((kt & 1) ? stg1 : stg0, khp, klp, vp, kt + 2, tid);
            CP_COMMIT();
        }
    }

    float rl0 = 1.f / l0, rl1 = 1.f / l1;
    size_t base0 = ((size_t)(b*TT + qr0) * CC) + h*64 + kc0;
    size_t base1 = base0 + (size_t)8 * CC;
    #pragma unroll
    for (int nt = 0; nt < 8; nt++) {
        *reinterpret_cast<__half2*>(y + base0 + nt*8) =
            __half2(__float2half(o[nt][0]*rl0), __float2half(o[nt][1]*rl0));
        *reinterpret_cast<__half2*>(y + base1 + nt*8) =
            __half2(__float2half(o[nt][2]*rl1), __float2half(o[nt][3]*rl1));
    }
}

// ================= launch =================
extern "C" void kernel_launch(void* const* d_in, const int* in_sizes, int n_in,
                              void* d_out, int out_size) {
    const float* x       = (const float*)d_in[0];
    const float* ln1_w   = (const float*)d_in[1];
    const float* ln1_b   = (const float*)d_in[2];
    const float* W_attn  = (const float*)d_in[3];
    const float* b_attn  = (const float*)d_in[4];
    const float* W_aproj = (const float*)d_in[5];
    const float* b_aproj = (const float*)d_in[6];
    const float* ln2_w   = (const float*)d_in[7];
    const float* ln2_b   = (const float*)d_in[8];
    const float* W_fc    = (const float*)d_in[9];
    const float* b_fc    = (const float*)d_in[10];
    const float* W_mproj = (const float*)d_in[11];
    const float* b_mproj = (const float*)d_in[12];
    float* out = (float*)d_out;

    float *x1, *mu, *inv;
    __half *y, *xth, *qh, *ql, *kh, *kl, *v, *yh, *hh, *fch;
    __half *wah, *wal, *wap, *wfc, *wmp;
    cudaGetSymbolAddress((void**)&y,   g_y);
    cudaGetSymbolAddress((void**)&x1,  g_x1);
    cudaGetSymbolAddress((void**)&mu,  g_mu);
    cudaGetSymbolAddress((void**)&inv, g_inv);
    cudaGetSymbolAddress((void**)&xth, g_xt_h);
    cudaGetSymbolAddress((void**)&yh,  g_yh);
    cudaGetSymbolAddress((void**)&hh,  g_hh);
    cudaGetSymbolAddress((void**)&fch, g_fch);
    cudaGetSymbolAddress((void**)&qh, g_qh); cudaGetSymbolAddress((void**)&ql, g_ql);
    cudaGetSymbolAddress((void**)&kh, g_kh); cudaGetSymbolAddress((void**)&kl, g_kl);
    cudaGetSymbolAddress((void**)&v,  g_v);
    cudaGetSymbolAddress((void**)&wah, g_wattn_h); cudaGetSymbolAddress((void**)&wal, g_wattn_l);
    cudaGetSymbolAddress((void**)&wap, g_waproj);
    cudaGetSymbolAddress((void**)&wfc, g_wfc);
    cudaGetSymbolAddress((void**)&wmp, g_wmproj);

    cudaFuncSetAttribute(attn_hmma, cudaFuncAttributeMaxDynamicSharedMemorySize, AT_SMEM);
    cudaFuncSetAttribute(gemm_qkv, cudaFuncAttributeMaxDynamicSharedMemorySize, QGSMEM);
    cudaFuncSetAttribute(gemm_fp16<1>, cudaFuncAttributeMaxDynamicSharedMemorySize, F1SMEM);
    cudaFuncSetAttribute(gemm_fp16<2>, cudaFuncAttributeMaxDynamicSharedMemorySize, F1SMEM);

    // ---- forked-stream prologue (graph-capture compatible) ----
    cudaStream_t s2;
    cudaStreamCreateWithFlags(&s2, cudaStreamNonBlocking);
    cudaEvent_t evFork, evAttnW, evAprW, evJoin;
    cudaEventCreateWithFlags(&evFork,  cudaEventDisableTiming);
    cudaEventCreateWithFlags(&evAttnW, cudaEventDisableTiming);
    cudaEventCreateWithFlags(&evAprW,  cudaEventDisableTiming);
    cudaEventCreateWithFlags(&evJoin,  cudaEventDisableTiming);

    cudaEventRecord(evFork, 0);
    cudaStreamWaitEvent(s2, evFork, 0);

    dim3 tb(32, 8);
    wsplit_h_kernel<<<dim3(3*CC/32, CC/32), tb, 0, s2>>>(W_attn, wah, wal, CC, 3*CC);
    cudaEventRecord(evAttnW, s2);
    wtrans_h_kernel<<<dim3(CC/32,   CC/32), tb, 0, s2>>>(W_aproj, wap, CC,   CC);
    cudaEventRecord(evAprW, s2);
    wtrans_h_kernel<<<dim3(4*CC/32, CC/32), tb, 0, s2>>>(W_fc,    wfc, CC,   4*CC);
    wtrans_h_kernel<<<dim3(CC/32, 4*CC/32), tb, 0, s2>>>(W_mproj, wmp, 4*CC, CC);
    cudaEventRecord(evJoin, s2);

    // main stream
    logmap_fused<<<NROWS, 256>>>(x, ln1_w, ln1_b, xth, mu, inv);
    cudaStreamWaitEvent(0, evAttnW, 0);
    gemm_qkv<<<dim3(3*CC/128, NROWS/128), 256, QGSMEM>>>(
        xth, wah, wal, b_attn, qh, ql, kh, kl, v);
    attn_hmma<<<dim3(TT/128, BB*HH), 256, AT_SMEM>>>(qh, ql, kh, kl, v, y);
    expmap_fused<<<NROWS, 256>>>(x, ln1_w, ln1_b, y, yh, mu, inv);
    cudaStreamWaitEvent(0, evAprW, 0);
    gemm_fp16<1><<<dim3(CC/128, NROWS/128), 256, F1SMEM>>>(
        yh, wap, b_aproj, x, x1, nullptr, CC, CC);
    ln_half_kernel<<<NROWS, 256>>>(x1, ln2_w, ln2_b, hh);
    cudaStreamWaitEvent(0, evJoin, 0);
    gemm_fp16<2><<<dim3(4*CC/128, NROWS/128), 256, F1SMEM>>>(
        hh, wfc, b_fc, nullptr, nullptr, fch, 4*CC, CC);
    gemm_fp16<1><<<dim3(CC/128, NROWS/128), 256, F1SMEM>>>(
        fch, wmp, b_mproj, x1, out, nullptr, CC, 4*CC);
}